// round 7
// baseline (speedup 1.0000x reference)
#include <cuda_runtime.h>
#include <math.h>

// Problem constants
#define TT    2048
#define HH    16
#define NOPE  128
#define ROPE  64
#define DQK   192
#define LORA  512
#define VDIM  128
#define QKSCALE 0.07216878364870323f   // 1/sqrt(192)

// Attention tiling
#define BQ   128
#define BKV  64
#define NWARP 8
#define QSTR 196    // Qs/Ks row stride: frag-load bank = 4g+q, conflict-free
#define VSTR 136    // Vs row stride: frag-load bank = 8q+g, conflict-free
#define PSTR 68     // P  row stride: frag-load bank = 4g+q, conflict-free

// Stage-1 GEMM smem strides
#define ASTR 36     // As row stride (32+4): frag bank 4g+q, fill float4-aligned
#define BSTR 132    // Bs row stride (128+4): frag bank 4q+g, fill coalesced

// Scratch: K (nope+rope, tf32-rounded, per head) and V (tf32-rounded)
__device__ float g_K[HH * TT * DQK];    // 25 MB
__device__ float g_V[HH * TT * VDIM];   // 16 MB

// ---------------------------------------------------------------------------
// tf32 + cp.async helpers
// ---------------------------------------------------------------------------
__device__ __forceinline__ unsigned f2tf(float f) {
    unsigned u;
    asm("cvt.rna.tf32.f32 %0, %1;" : "=r"(u) : "f"(f));
    return u;
}

#define CP16(dst_u32, src_ptr) \
    asm volatile("cp.async.cg.shared.global [%0], [%1], 16;\n" \
                 :: "r"(dst_u32), "l"(src_ptr))
#define CP_COMMIT() asm volatile("cp.async.commit_group;\n" ::)
#define CP_WAIT1()  asm volatile("cp.async.wait_group 1;\n" ::)

__device__ __forceinline__ void mma_tf32(float* c,
    unsigned a0, unsigned a1, unsigned a2, unsigned a3,
    unsigned b0, unsigned b1)
{
    asm volatile(
        "mma.sync.aligned.m16n8k8.row.col.f32.tf32.tf32.f32 "
        "{%0,%1,%2,%3}, {%4,%5,%6,%7}, {%8,%9}, {%0,%1,%2,%3};\n"
        : "+f"(c[0]), "+f"(c[1]), "+f"(c[2]), "+f"(c[3])
        : "r"(a0), "r"(a1), "r"(a2), "r"(a3), "r"(b0), "r"(b1));
}

// ---------------------------------------------------------------------------
// Stage 1: C(2048 x 4096) = k_c(2048 x 512) @ B(512 x 4096), tf32 MMA with
// 2-term split on A (exact), single-rounded B. Output tf32-rounded to g_K/g_V.
// Block 128x128, 8 warps (4m x 2n), k-chunk 32.
// ---------------------------------------------------------------------------
__global__ __launch_bounds__(256, 2) void kv_gemm_kernel(
    const float* __restrict__ kc,
    const float* __restrict__ wkv,
    const float* __restrict__ wuv)
{
    extern __shared__ unsigned gs[];
    unsigned* As_hi = gs;                       // 128 * ASTR
    unsigned* As_lo = As_hi + 128 * ASTR;       // 128 * ASTR
    unsigned* Bs_hi = As_lo + 128 * ASTR;       // 32 * BSTR  (k-major)

    const int bn  = blockIdx.x * 128;
    const int bm  = blockIdx.y * 128;
    const bool isV = (bn & 128) != 0;
    const int h   = bn >> 8;

    const int tid  = threadIdx.x;
    const int w    = tid >> 5;
    const int lane = tid & 31;
    const int g    = lane >> 2;
    const int q    = lane & 3;
    const int wm   = w & 3;          // 4 m-warps
    const int wn   = w >> 2;         // 2 n-warps
    const int m0   = wm * 32;
    const int n0   = wn * 64;

    float acc[2][8][4];
#pragma unroll
    for (int mt = 0; mt < 2; mt++)
#pragma unroll
        for (int nt = 0; nt < 8; nt++)
#pragma unroll
            for (int i = 0; i < 4; i++) acc[mt][nt][i] = 0.f;

    for (int kt = 0; kt < LORA; kt += 32) {
        // ---- fill A (128x32): hi/lo split at fill time ----
#pragma unroll
        for (int i = 0; i < 4; i++) {
            int idx = tid + i * 256;           // 1024 float4
            int r = idx >> 3, c4 = idx & 7;
            float4 v = *(const float4*)&kc[(size_t)(bm + r) * LORA + kt + c4 * 4];
            unsigned h0 = f2tf(v.x), h1 = f2tf(v.y), h2 = f2tf(v.z), h3 = f2tf(v.w);
            unsigned l0 = f2tf(v.x - __uint_as_float(h0));
            unsigned l1 = f2tf(v.y - __uint_as_float(h1));
            unsigned l2 = f2tf(v.z - __uint_as_float(h2));
            unsigned l3 = f2tf(v.w - __uint_as_float(h3));
            unsigned* dh = &As_hi[r * ASTR + c4 * 4];
            unsigned* dl = &As_lo[r * ASTR + c4 * 4];
            *(uint4*)dh = make_uint4(h0, h1, h2, h3);
            *(uint4*)dl = make_uint4(l0, l1, l2, l3);
        }
        // ---- fill B (32k x 128n, k-major) ----
#pragma unroll
        for (int i = 0; i < 4; i++) {
            int idx = tid + i * 256;           // 1024 float4
            int k = idx >> 5, j4 = idx & 31;
            float4 v;
            if (isV) v = *(const float4*)&wuv[((size_t)h * LORA + kt + k) * VDIM + j4 * 4];
            else     v = *(const float4*)&wkv[(size_t)(kt + k) * (HH * 256) + bn + j4 * 4];
            unsigned* d = &Bs_hi[k * BSTR + j4 * 4];
            *(uint4*)d = make_uint4(f2tf(v.x), f2tf(v.y), f2tf(v.z), f2tf(v.w));
        }
        __syncthreads();

        // ---- MMA over 4 k-steps ----
#pragma unroll
        for (int ks = 0; ks < 4; ks++) {
            const int k0 = ks * 8;
            unsigned ah[2][4], al[2][4];
#pragma unroll
            for (int mt = 0; mt < 2; mt++) {
                int rb = (m0 + mt * 16 + g) * ASTR + k0 + q;
                ah[mt][0] = As_hi[rb];               ah[mt][1] = As_hi[rb + 8 * ASTR];
                ah[mt][2] = As_hi[rb + 4];           ah[mt][3] = As_hi[rb + 8 * ASTR + 4];
                al[mt][0] = As_lo[rb];               al[mt][1] = As_lo[rb + 8 * ASTR];
                al[mt][2] = As_lo[rb + 4];           al[mt][3] = As_lo[rb + 8 * ASTR + 4];
            }
#pragma unroll
            for (int nt = 0; nt < 8; nt++) {
                int cb = (k0 + q) * BSTR + n0 + nt * 8 + g;
                unsigned b0 = Bs_hi[cb];
                unsigned b1 = Bs_hi[cb + 4 * BSTR];
#pragma unroll
                for (int mt = 0; mt < 2; mt++) {
                    mma_tf32(acc[mt][nt], ah[mt][0], ah[mt][1], ah[mt][2], ah[mt][3], b0, b1);
                    mma_tf32(acc[mt][nt], al[mt][0], al[mt][1], al[mt][2], al[mt][3], b0, b1);
                }
            }
        }
        __syncthreads();
    }

    // ---- epilogue: tf32-round and store to g_K / g_V ----
#pragma unroll
    for (int mt = 0; mt < 2; mt++) {
        int row0 = bm + m0 + mt * 16 + g;
        int row1 = row0 + 8;
#pragma unroll
        for (int nt = 0; nt < 8; nt++) {
            int col = n0 + nt * 8 + 2 * q;     // 0..127 within block
            float c0 = __uint_as_float(f2tf(acc[mt][nt][0]));
            float c1 = __uint_as_float(f2tf(acc[mt][nt][1]));
            float c2 = __uint_as_float(f2tf(acc[mt][nt][2]));
            float c3 = __uint_as_float(f2tf(acc[mt][nt][3]));
            if (isV) {
                *(float2*)&g_V[((size_t)(h * TT + row0)) * VDIM + col] = make_float2(c0, c1);
                *(float2*)&g_V[((size_t)(h * TT + row1)) * VDIM + col] = make_float2(c2, c3);
            } else {
                *(float2*)&g_K[((size_t)(h * TT + row0)) * DQK + col] = make_float2(c0, c1);
                *(float2*)&g_K[((size_t)(h * TT + row1)) * DQK + col] = make_float2(c2, c3);
            }
        }
    }
}

// ---------------------------------------------------------------------------
// Rope fill (float4): replicate k_pe into g_K cols [128,192) per head (tf32).
// ---------------------------------------------------------------------------
__global__ __launch_bounds__(256) void rope_fill_kernel(const float* __restrict__ kpe)
{
    int idx = blockIdx.x * 256 + threadIdx.x;     // HH*TT*16 float4s
    if (idx >= HH * TT * 16) return;
    int h   = idx >> 15;            // TT*16 = 32768
    int rem = idx & 32767;
    int t   = rem >> 4;
    int c4  = rem & 15;
    float4 v = *(const float4*)&kpe[t * ROPE + c4 * 4];
    float4 o;
    o.x = __uint_as_float(f2tf(v.x));
    o.y = __uint_as_float(f2tf(v.y));
    o.z = __uint_as_float(f2tf(v.z));
    o.w = __uint_as_float(f2tf(v.w));
    *(float4*)&g_K[((size_t)(h * TT + t)) * DQK + NOPE + c4 * 4] = o;
}

// ---------------------------------------------------------------------------
// Stage 2: causal flash attention, tf32 MMA, 8 warps, cp.async pipelined.
// (unchanged from round 6)
// ---------------------------------------------------------------------------
__global__ __launch_bounds__(256, 1) void attn_kernel(
    const float* __restrict__ query,
    float* __restrict__ out)
{
    extern __shared__ unsigned sm[];
    unsigned* Qs = sm;                       // BQ  * QSTR
    unsigned* Ks = Qs + BQ * QSTR;           // BKV * QSTR
    unsigned* Vs = Ks + BKV * QSTR;          // BKV * VSTR
    unsigned* Ps = Vs + BKV * VSTR;          // NWARP * 16 * PSTR

    const int h    = blockIdx.y;
    const int qt   = (int)gridDim.x - 1 - (int)blockIdx.x;  // heavy tiles first
    const int q0   = qt * BQ;
    const int tid  = threadIdx.x;
    const int w    = tid >> 5;
    const int lane = tid & 31;
    const int g    = lane >> 2;
    const int q    = lane & 3;
    unsigned* Pw   = Ps + w * 16 * PSTR;

    const unsigned Ks_u = (unsigned)__cvta_generic_to_shared(Ks);
    const unsigned Vs_u = (unsigned)__cvta_generic_to_shared(Vs);

    const float* gKh = g_K + (size_t)h * TT * DQK;
    const float* gVh = g_V + (size_t)h * TT * VDIM;

    const int ntile = 2 * qt + 2;

    // ---- prologue: Q load (tf32) + first K/V cp.async ----
    for (int idx = tid; idx < BQ * 48; idx += 256) {
        int r = idx / 48, cw = idx - r * 48;
        float4 v = *(const float4*)&query[((size_t)(q0 + r) * HH + h) * DQK + cw * 4];
        unsigned* d = &Qs[r * QSTR + cw * 4];
        d[0] = f2tf(v.x); d[1] = f2tf(v.y); d[2] = f2tf(v.z); d[3] = f2tf(v.w);
    }
    {   // K tile 0
        const float* base = gKh;
#pragma unroll
        for (int i = 0; i < 12; i++) {
            int idx = tid + i * 256;
            int r = idx / 48, cw = idx - r * 48;
            CP16(Ks_u + (unsigned)(r * QSTR + cw * 4) * 4u, base + r * DQK + cw * 4);
        }
        CP_COMMIT();
    }
    {   // V tile 0
        const float* base = gVh;
#pragma unroll
        for (int i = 0; i < 8; i++) {
            int idx = tid + i * 256;
            int r = idx >> 5, cw = idx & 31;
            CP16(Vs_u + (unsigned)(r * VSTR + cw * 4) * 4u, base + r * VDIM + cw * 4);
        }
        CP_COMMIT();
    }

    float oAcc[16][4];
#pragma unroll
    for (int n = 0; n < 16; n++)
#pragma unroll
        for (int i = 0; i < 4; i++) oAcc[n][i] = 0.f;

    float m_lo = -INFINITY, m_hi = -INFINITY;
    float l_lo = 0.f, l_hi = 0.f;

    const int row_lo   = q0 + w * 16 + g;
    const int row_hi   = row_lo + 8;
    const int rowmax_w = q0 + w * 16 + 15;

    float sA[8][4];

    for (int kt = 0; kt < ntile; kt++) {
        const int s0 = kt * BKV;
        const bool active = (s0 <= rowmax_w);

        CP_WAIT1();            // K(kt) arrived   (pending: V(kt))
        __syncthreads();       // K visible to all warps; Qs ready (kt==0)

        // ---- S = Q @ K^T ----
        if (active) {
#pragma unroll
            for (int n = 0; n < 8; n++)
#pragma unroll
                for (int i = 0; i < 4; i++) sA[n][i] = 0.f;
#pragma unroll
            for (int kb = 0; kb < DQK / 8; kb++) {
                const int k0 = kb * 8;
                unsigned a0 = Qs[(w * 16 + g    ) * QSTR + k0 + q    ];
                unsigned a1 = Qs[(w * 16 + g + 8) * QSTR + k0 + q    ];
                unsigned a2 = Qs[(w * 16 + g    ) * QSTR + k0 + q + 4];
                unsigned a3 = Qs[(w * 16 + g + 8) * QSTR + k0 + q + 4];
#pragma unroll
                for (int n = 0; n < 8; n++) {
                    unsigned b0 = Ks[(n * 8 + g) * QSTR + k0 + q    ];
                    unsigned b1 = Ks[(n * 8 + g) * QSTR + k0 + q + 4];
                    mma_tf32(sA[n], a0, a1, a2, a3, b0, b1);
                }
            }
        }
        __syncthreads();       // all warps done reading Ks

        // ---- prefetch K(kt+1) while we do softmax + PV ----
        if (kt + 1 < ntile) {
            const float* base = gKh + (size_t)(s0 + BKV) * DQK;
#pragma unroll
            for (int i = 0; i < 12; i++) {
                int idx = tid + i * 256;
                int r = idx / 48, cw = idx - r * 48;
                CP16(Ks_u + (unsigned)(r * QSTR + cw * 4) * 4u, base + r * DQK + cw * 4);
            }
        }
        CP_COMMIT();           // pending: V(kt), K(kt+1)

        if (active) {
            // ---- scale + causal mask ----
#pragma unroll
            for (int n = 0; n < 8; n++) {
                int c0 = s0 + n * 8 + 2 * q;
                sA[n][0] = (c0     <= row_lo) ? sA[n][0] * QKSCALE : -1.0e30f;
                sA[n][1] = (c0 + 1 <= row_lo) ? sA[n][1] * QKSCALE : -1.0e30f;
                sA[n][2] = (c0     <= row_hi) ? sA[n][2] * QKSCALE : -1.0e30f;
                sA[n][3] = (c0 + 1 <= row_hi) ? sA[n][3] * QKSCALE : -1.0e30f;
            }

            // ---- online softmax in registers ----
            float tm_lo = -1.0e30f, tm_hi = -1.0e30f;
#pragma unroll
            for (int n = 0; n < 8; n++) {
                tm_lo = fmaxf(tm_lo, fmaxf(sA[n][0], sA[n][1]));
                tm_hi = fmaxf(tm_hi, fmaxf(sA[n][2], sA[n][3]));
            }
            tm_lo = fmaxf(tm_lo, __shfl_xor_sync(0xffffffffu, tm_lo, 1));
            tm_lo = fmaxf(tm_lo, __shfl_xor_sync(0xffffffffu, tm_lo, 2));
            tm_hi = fmaxf(tm_hi, __shfl_xor_sync(0xffffffffu, tm_hi, 1));
            tm_hi = fmaxf(tm_hi, __shfl_xor_sync(0xffffffffu, tm_hi, 2));

            float mn_lo = fmaxf(m_lo, tm_lo);
            float mn_hi = fmaxf(m_hi, tm_hi);
            float sc_lo = __expf(m_lo - mn_lo);
            float sc_hi = __expf(m_hi - mn_hi);

            float sum_lo = 0.f, sum_hi = 0.f;
#pragma unroll
            for (int n = 0; n < 8; n++) {
                sA[n][0] = __expf(sA[n][0] - mn_lo);
                sA[n][1] = __expf(sA[n][1] - mn_lo);
                sA[n][2] = __expf(sA[n][2] - mn_hi);
                sA[n][3] = __expf(sA[n][3] - mn_hi);
                sum_lo += sA[n][0] + sA[n][1];
                sum_hi += sA[n][2] + sA[n][3];
            }
            sum_lo += __shfl_xor_sync(0xffffffffu, sum_lo, 1);
            sum_lo += __shfl_xor_sync(0xffffffffu, sum_lo, 2);
            sum_hi += __shfl_xor_sync(0xffffffffu, sum_hi, 1);
            sum_hi += __shfl_xor_sync(0xffffffffu, sum_hi, 2);

            l_lo = l_lo * sc_lo + sum_lo;  m_lo = mn_lo;
            l_hi = l_hi * sc_hi + sum_hi;  m_hi = mn_hi;

#pragma unroll
            for (int n = 0; n < 16; n++) {
                oAcc[n][0] *= sc_lo;  oAcc[n][1] *= sc_lo;
                oAcc[n][2] *= sc_hi;  oAcc[n][3] *= sc_hi;
            }

            // ---- write P (tf32) to warp-private smem ----
            __syncwarp();
#pragma unroll
            for (int n = 0; n < 8; n++) {
                uint2 plo = make_uint2(f2tf(sA[n][0]), f2tf(sA[n][1]));
                uint2 phi = make_uint2(f2tf(sA[n][2]), f2tf(sA[n][3]));
                *(uint2*)&Pw[(g    ) * PSTR + n * 8 + 2 * q] = plo;
                *(uint2*)&Pw[(g + 8) * PSTR + n * 8 + 2 * q] = phi;
            }
            __syncwarp();
        }

        CP_WAIT1();            // V(kt) arrived   (pending: K(kt+1))
        __syncthreads();       // V visible

        // ---- O += P @ V ----
        if (active) {
#pragma unroll
            for (int kb = 0; kb < BKV / 8; kb++) {
                const int k0 = kb * 8;
                unsigned a0 = Pw[(g    ) * PSTR + k0 + q    ];
                unsigned a1 = Pw[(g + 8) * PSTR + k0 + q    ];
                unsigned a2 = Pw[(g    ) * PSTR + k0 + q + 4];
                unsigned a3 = Pw[(g + 8) * PSTR + k0 + q + 4];
#pragma unroll
                for (int n = 0; n < 16; n++) {
                    unsigned b0 = Vs[(k0 + q    ) * VSTR + n * 8 + g];
                    unsigned b1 = Vs[(k0 + q + 4) * VSTR + n * 8 + g];
                    mma_tf32(oAcc[n], a0, a1, a2, a3, b0, b1);
                }
            }
        }
        __syncthreads();       // all warps done reading Vs

        // ---- prefetch V(kt+1) ----
        if (kt + 1 < ntile) {
            const float* base = gVh + (size_t)(s0 + BKV) * VDIM;
#pragma unroll
            for (int i = 0; i < 8; i++) {
                int idx = tid + i * 256;
                int r = idx >> 5, cw = idx & 31;
                CP16(Vs_u + (unsigned)(r * VSTR + cw * 4) * 4u, base + r * VDIM + cw * 4);
            }
        }
        CP_COMMIT();           // pending: K(kt+1), V(kt+1)
    }

    // ---- epilogue: normalize + store ----
    const float il_lo = 1.0f / l_lo;
    const float il_hi = 1.0f / l_hi;
#pragma unroll
    for (int n = 0; n < 16; n++) {
        int col = h * VDIM + n * 8 + 2 * q;
        float2 vlo = make_float2(oAcc[n][0] * il_lo, oAcc[n][1] * il_lo);
        float2 vhi = make_float2(oAcc[n][2] * il_hi, oAcc[n][3] * il_hi);
        *(float2*)&out[(size_t)row_lo * (HH * VDIM) + col] = vlo;
        *(float2*)&out[(size_t)row_hi * (HH * VDIM) + col] = vhi;
    }
}

// ---------------------------------------------------------------------------
extern "C" void kernel_launch(void* const* d_in, const int* in_sizes, int n_in,
                              void* d_out, int out_size)
{
    const float* query = (const float*)d_in[0];  // (T, H, 192)
    const float* kc    = (const float*)d_in[1];  // (T, 512)
    const float* kpe   = (const float*)d_in[2];  // (T, 64)
    const float* wkv   = (const float*)d_in[3];  // (512, 4096)
    const float* wuv   = (const float*)d_in[4];  // (16, 512, 128)
    float* out = (float*)d_out;                  // (T, 2048)

    rope_fill_kernel<<<(HH * TT * 16 + 255) / 256, 256>>>(kpe);

    size_t gsmem = (size_t)(2 * 128 * ASTR + 32 * BSTR) * sizeof(unsigned); // ~54 KB
    cudaFuncSetAttribute(kv_gemm_kernel,
                         cudaFuncAttributeMaxDynamicSharedMemorySize, (int)gsmem);
    kv_gemm_kernel<<<dim3(32, 16), 256, gsmem>>>(kc, wkv, wuv);

    size_t smem = (size_t)(BQ * QSTR + BKV * QSTR + BKV * VSTR + NWARP * 16 * PSTR)
                  * sizeof(unsigned);   // 220,160 B
    cudaFuncSetAttribute(attn_kernel,
                         cudaFuncAttributeMaxDynamicSharedMemorySize, (int)smem);
    attn_kernel<<<dim3(TT / BQ, HH), 256, smem>>>(query, out);
}

// round 8
// speedup vs baseline: 1.4646x; 1.4646x over previous
#include <cuda_runtime.h>
#include <math.h>

// Problem constants
#define TT    2048
#define HH    16
#define NOPE  128
#define ROPE  64
#define DQK   192
#define LORA  512
#define VDIM  128
#define QKSCALE 0.07216878364870323f   // 1/sqrt(192)

// Attention tiling
#define BQ   128
#define BKV  64
#define NWARP 8
#define QSTR 196    // Qs/Ks row stride: frag-load bank = 4g+q, conflict-free
#define VSTR 136    // Vs row stride: frag-load bank = 8q+g, conflict-free
#define PSTR 68     // P  row stride: frag-load bank = 4g+q, conflict-free

// Stage-1 GEMM smem strides / buffer geometry
#define ASTR 36     // As row stride (32+4): frag bank 4g+q, fill float4-aligned
#define BSTR 132    // Bs row stride (128+4): frag bank 4q+g, fill coalesced
#define AHSZ (128 * ASTR)
#define GBUF (2 * AHSZ + 32 * BSTR)    // As_hi + As_lo + Bs = 13440 words

// Scratch: K (nope+rope, tf32-rounded, per head) and V (tf32-rounded)
__device__ float g_K[HH * TT * DQK];    // 25 MB
__device__ float g_V[HH * TT * VDIM];   // 16 MB

// ---------------------------------------------------------------------------
// tf32 + cp.async helpers
// ---------------------------------------------------------------------------
__device__ __forceinline__ unsigned f2tf(float f) {
    unsigned u;
    asm("cvt.rna.tf32.f32 %0, %1;" : "=r"(u) : "f"(f));
    return u;
}

#define CP16(dst_u32, src_ptr) \
    asm volatile("cp.async.cg.shared.global [%0], [%1], 16;\n" \
                 :: "r"(dst_u32), "l"(src_ptr))
#define CP_COMMIT() asm volatile("cp.async.commit_group;\n" ::)
#define CP_WAIT1()  asm volatile("cp.async.wait_group 1;\n" ::)

__device__ __forceinline__ void mma_tf32(float* c,
    unsigned a0, unsigned a1, unsigned a2, unsigned a3,
    unsigned b0, unsigned b1)
{
    asm volatile(
        "mma.sync.aligned.m16n8k8.row.col.f32.tf32.tf32.f32 "
        "{%0,%1,%2,%3}, {%4,%5,%6,%7}, {%8,%9}, {%0,%1,%2,%3};\n"
        : "+f"(c[0]), "+f"(c[1]), "+f"(c[2]), "+f"(c[3])
        : "r"(a0), "r"(a1), "r"(a2), "r"(a3), "r"(b0), "r"(b1));
}

// ---------------------------------------------------------------------------
// Stage 1: C(2048 x 4096) = k_c(2048 x 512) @ B(512 x 4096), tf32 MMA,
// 2-term split on A (exact), single-rounded B. Double-buffered smem with
// register-staged global prefetch: one __syncthreads per k-chunk, LDG for
// chunk kt+1 issued before the MMA block of chunk kt.
// Block 128x128, 8 warps (4m x 2n), k-chunk 32.
// ---------------------------------------------------------------------------
__global__ __launch_bounds__(256, 1) void kv_gemm_kernel(
    const float* __restrict__ kc,
    const float* __restrict__ wkv,
    const float* __restrict__ wuv)
{
    extern __shared__ unsigned gs[];   // 2 buffers of GBUF words

    const int bn  = blockIdx.x * 128;
    const int bm  = blockIdx.y * 128;
    const bool isV = (bn & 128) != 0;
    const int h   = bn >> 8;

    const int tid  = threadIdx.x;
    const int w    = tid >> 5;
    const int lane = tid & 31;
    const int g    = lane >> 2;
    const int q    = lane & 3;
    const int wm   = w & 3;          // 4 m-warps
    const int wn   = w >> 2;         // 2 n-warps
    const int m0   = wm * 32;
    const int n0   = wn * 64;

    // Per-thread fill coordinates (fixed across chunks)
    const int ar  = tid >> 3;          // A row pair base: rows ar, ar+32, ar+64, ar+96
    const int ac4 = tid & 7;           // A col group (float4)
    const int bk  = tid >> 5;          // B k rows: bk, bk+8, bk+16, bk+24
    const int bj4 = tid & 31;          // B col group (float4)

    float4 aReg[4], bReg[4];

    // ---- load chunk 0 into registers ----
#pragma unroll
    for (int i = 0; i < 4; i++)
        aReg[i] = *(const float4*)&kc[(size_t)(bm + ar + i * 32) * LORA + ac4 * 4];
#pragma unroll
    for (int i = 0; i < 4; i++) {
        int k = bk + i * 8;
        if (isV) bReg[i] = *(const float4*)&wuv[((size_t)h * LORA + k) * VDIM + bj4 * 4];
        else     bReg[i] = *(const float4*)&wkv[(size_t)k * (HH * 256) + bn + bj4 * 4];
    }

    float acc[2][8][4];
#pragma unroll
    for (int mt = 0; mt < 2; mt++)
#pragma unroll
        for (int nt = 0; nt < 8; nt++)
#pragma unroll
            for (int i = 0; i < 4; i++) acc[mt][nt][i] = 0.f;

    // ---- convert + store chunk 0 into buffer 0 ----
    {
        unsigned* As_hi = gs;
        unsigned* As_lo = gs + AHSZ;
        unsigned* Bs    = gs + 2 * AHSZ;
#pragma unroll
        for (int i = 0; i < 4; i++) {
            float4 v = aReg[i];
            unsigned h0 = f2tf(v.x), h1 = f2tf(v.y), h2 = f2tf(v.z), h3 = f2tf(v.w);
            unsigned l0 = f2tf(v.x - __uint_as_float(h0));
            unsigned l1 = f2tf(v.y - __uint_as_float(h1));
            unsigned l2 = f2tf(v.z - __uint_as_float(h2));
            unsigned l3 = f2tf(v.w - __uint_as_float(h3));
            *(uint4*)&As_hi[(ar + i * 32) * ASTR + ac4 * 4] = make_uint4(h0, h1, h2, h3);
            *(uint4*)&As_lo[(ar + i * 32) * ASTR + ac4 * 4] = make_uint4(l0, l1, l2, l3);
        }
#pragma unroll
        for (int i = 0; i < 4; i++) {
            float4 v = bReg[i];
            *(uint4*)&Bs[(bk + i * 8) * BSTR + bj4 * 4] =
                make_uint4(f2tf(v.x), f2tf(v.y), f2tf(v.z), f2tf(v.w));
        }
    }

    for (int kt = 0; kt < 16; kt++) {
        __syncthreads();   // current buffer's STS complete (all threads)

        // ---- prefetch chunk kt+1 into registers (LDG issued before MMA) ----
        if (kt < 15) {
            const int k1 = (kt + 1) * 32;
#pragma unroll
            for (int i = 0; i < 4; i++)
                aReg[i] = *(const float4*)&kc[(size_t)(bm + ar + i * 32) * LORA + k1 + ac4 * 4];
#pragma unroll
            for (int i = 0; i < 4; i++) {
                int k = k1 + bk + i * 8;
                if (isV) bReg[i] = *(const float4*)&wuv[((size_t)h * LORA + k) * VDIM + bj4 * 4];
                else     bReg[i] = *(const float4*)&wkv[(size_t)k * (HH * 256) + bn + bj4 * 4];
            }
        }

        // ---- MMA on current buffer ----
        unsigned* As_hi = gs + (kt & 1) * GBUF;
        unsigned* As_lo = As_hi + AHSZ;
        unsigned* Bs    = As_hi + 2 * AHSZ;
#pragma unroll
        for (int ks = 0; ks < 4; ks++) {
            const int k0 = ks * 8;
            unsigned ah[2][4], al[2][4];
#pragma unroll
            for (int mt = 0; mt < 2; mt++) {
                int rb = (m0 + mt * 16 + g) * ASTR + k0 + q;
                ah[mt][0] = As_hi[rb];               ah[mt][1] = As_hi[rb + 8 * ASTR];
                ah[mt][2] = As_hi[rb + 4];           ah[mt][3] = As_hi[rb + 8 * ASTR + 4];
                al[mt][0] = As_lo[rb];               al[mt][1] = As_lo[rb + 8 * ASTR];
                al[mt][2] = As_lo[rb + 4];           al[mt][3] = As_lo[rb + 8 * ASTR + 4];
            }
#pragma unroll
            for (int nt = 0; nt < 8; nt++) {
                int cb = (k0 + q) * BSTR + n0 + nt * 8 + g;
                unsigned b0 = Bs[cb];
                unsigned b1 = Bs[cb + 4 * BSTR];
#pragma unroll
                for (int mt = 0; mt < 2; mt++) {
                    mma_tf32(acc[mt][nt], ah[mt][0], ah[mt][1], ah[mt][2], ah[mt][3], b0, b1);
                    mma_tf32(acc[mt][nt], al[mt][0], al[mt][1], al[mt][2], al[mt][3], b0, b1);
                }
            }
        }

        // ---- convert + store chunk kt+1 into the other buffer ----
        if (kt < 15) {
            unsigned* nAs_hi = gs + ((kt + 1) & 1) * GBUF;
            unsigned* nAs_lo = nAs_hi + AHSZ;
            unsigned* nBs    = nAs_hi + 2 * AHSZ;
#pragma unroll
            for (int i = 0; i < 4; i++) {
                float4 v = aReg[i];
                unsigned h0 = f2tf(v.x), h1 = f2tf(v.y), h2 = f2tf(v.z), h3 = f2tf(v.w);
                unsigned l0 = f2tf(v.x - __uint_as_float(h0));
                unsigned l1 = f2tf(v.y - __uint_as_float(h1));
                unsigned l2 = f2tf(v.z - __uint_as_float(h2));
                unsigned l3 = f2tf(v.w - __uint_as_float(h3));
                *(uint4*)&nAs_hi[(ar + i * 32) * ASTR + ac4 * 4] = make_uint4(h0, h1, h2, h3);
                *(uint4*)&nAs_lo[(ar + i * 32) * ASTR + ac4 * 4] = make_uint4(l0, l1, l2, l3);
            }
#pragma unroll
            for (int i = 0; i < 4; i++) {
                float4 v = bReg[i];
                *(uint4*)&nBs[(bk + i * 8) * BSTR + bj4 * 4] =
                    make_uint4(f2tf(v.x), f2tf(v.y), f2tf(v.z), f2tf(v.w));
            }
        }
    }

    // ---- epilogue: tf32-round and store to g_K / g_V ----
#pragma unroll
    for (int mt = 0; mt < 2; mt++) {
        int row0 = bm + m0 + mt * 16 + g;
        int row1 = row0 + 8;
#pragma unroll
        for (int nt = 0; nt < 8; nt++) {
            int col = n0 + nt * 8 + 2 * q;
            float c0 = __uint_as_float(f2tf(acc[mt][nt][0]));
            float c1 = __uint_as_float(f2tf(acc[mt][nt][1]));
            float c2 = __uint_as_float(f2tf(acc[mt][nt][2]));
            float c3 = __uint_as_float(f2tf(acc[mt][nt][3]));
            if (isV) {
                *(float2*)&g_V[((size_t)(h * TT + row0)) * VDIM + col] = make_float2(c0, c1);
                *(float2*)&g_V[((size_t)(h * TT + row1)) * VDIM + col] = make_float2(c2, c3);
            } else {
                *(float2*)&g_K[((size_t)(h * TT + row0)) * DQK + col] = make_float2(c0, c1);
                *(float2*)&g_K[((size_t)(h * TT + row1)) * DQK + col] = make_float2(c2, c3);
            }
        }
    }
}

// ---------------------------------------------------------------------------
// Rope fill (float4): replicate k_pe into g_K cols [128,192) per head (tf32).
// ---------------------------------------------------------------------------
__global__ __launch_bounds__(256) void rope_fill_kernel(const float* __restrict__ kpe)
{
    int idx = blockIdx.x * 256 + threadIdx.x;     // HH*TT*16 float4s
    if (idx >= HH * TT * 16) return;
    int h   = idx >> 15;            // TT*16 = 32768
    int rem = idx & 32767;
    int t   = rem >> 4;
    int c4  = rem & 15;
    float4 v = *(const float4*)&kpe[t * ROPE + c4 * 4];
    float4 o;
    o.x = __uint_as_float(f2tf(v.x));
    o.y = __uint_as_float(f2tf(v.y));
    o.z = __uint_as_float(f2tf(v.z));
    o.w = __uint_as_float(f2tf(v.w));
    *(float4*)&g_K[((size_t)(h * TT + t)) * DQK + NOPE + c4 * 4] = o;
}

// ---------------------------------------------------------------------------
// Stage 2: causal flash attention, tf32 MMA, 8 warps, cp.async pipelined.
// (unchanged — round-6 proven config)
// ---------------------------------------------------------------------------
__global__ __launch_bounds__(256, 1) void attn_kernel(
    const float* __restrict__ query,
    float* __restrict__ out)
{
    extern __shared__ unsigned sm[];
    unsigned* Qs = sm;                       // BQ  * QSTR
    unsigned* Ks = Qs + BQ * QSTR;           // BKV * QSTR
    unsigned* Vs = Ks + BKV * QSTR;          // BKV * VSTR
    unsigned* Ps = Vs + BKV * VSTR;          // NWARP * 16 * PSTR

    const int h    = blockIdx.y;
    const int qt   = (int)gridDim.x - 1 - (int)blockIdx.x;  // heavy tiles first
    const int q0   = qt * BQ;
    const int tid  = threadIdx.x;
    const int w    = tid >> 5;
    const int lane = tid & 31;
    const int g    = lane >> 2;
    const int q    = lane & 3;
    unsigned* Pw   = Ps + w * 16 * PSTR;

    const unsigned Ks_u = (unsigned)__cvta_generic_to_shared(Ks);
    const unsigned Vs_u = (unsigned)__cvta_generic_to_shared(Vs);

    const float* gKh = g_K + (size_t)h * TT * DQK;
    const float* gVh = g_V + (size_t)h * TT * VDIM;

    const int ntile = 2 * qt + 2;

    // ---- prologue: Q load (tf32) + first K/V cp.async ----
    for (int idx = tid; idx < BQ * 48; idx += 256) {
        int r = idx / 48, cw = idx - r * 48;
        float4 v = *(const float4*)&query[((size_t)(q0 + r) * HH + h) * DQK + cw * 4];
        unsigned* d = &Qs[r * QSTR + cw * 4];
        d[0] = f2tf(v.x); d[1] = f2tf(v.y); d[2] = f2tf(v.z); d[3] = f2tf(v.w);
    }
    {   // K tile 0
        const float* base = gKh;
#pragma unroll
        for (int i = 0; i < 12; i++) {
            int idx = tid + i * 256;
            int r = idx / 48, cw = idx - r * 48;
            CP16(Ks_u + (unsigned)(r * QSTR + cw * 4) * 4u, base + r * DQK + cw * 4);
        }
        CP_COMMIT();
    }
    {   // V tile 0
        const float* base = gVh;
#pragma unroll
        for (int i = 0; i < 8; i++) {
            int idx = tid + i * 256;
            int r = idx >> 5, cw = idx & 31;
            CP16(Vs_u + (unsigned)(r * VSTR + cw * 4) * 4u, base + r * VDIM + cw * 4);
        }
        CP_COMMIT();
    }

    float oAcc[16][4];
#pragma unroll
    for (int n = 0; n < 16; n++)
#pragma unroll
        for (int i = 0; i < 4; i++) oAcc[n][i] = 0.f;

    float m_lo = -INFINITY, m_hi = -INFINITY;
    float l_lo = 0.f, l_hi = 0.f;

    const int row_lo   = q0 + w * 16 + g;
    const int row_hi   = row_lo + 8;
    const int rowmax_w = q0 + w * 16 + 15;

    float sA[8][4];

    for (int kt = 0; kt < ntile; kt++) {
        const int s0 = kt * BKV;
        const bool active = (s0 <= rowmax_w);

        CP_WAIT1();            // K(kt) arrived   (pending: V(kt))
        __syncthreads();       // K visible to all warps; Qs ready (kt==0)

        // ---- S = Q @ K^T ----
        if (active) {
#pragma unroll
            for (int n = 0; n < 8; n++)
#pragma unroll
                for (int i = 0; i < 4; i++) sA[n][i] = 0.f;
#pragma unroll
            for (int kb = 0; kb < DQK / 8; kb++) {
                const int k0 = kb * 8;
                unsigned a0 = Qs[(w * 16 + g    ) * QSTR + k0 + q    ];
                unsigned a1 = Qs[(w * 16 + g + 8) * QSTR + k0 + q    ];
                unsigned a2 = Qs[(w * 16 + g    ) * QSTR + k0 + q + 4];
                unsigned a3 = Qs[(w * 16 + g + 8) * QSTR + k0 + q + 4];
#pragma unroll
                for (int n = 0; n < 8; n++) {
                    unsigned b0 = Ks[(n * 8 + g) * QSTR + k0 + q    ];
                    unsigned b1 = Ks[(n * 8 + g) * QSTR + k0 + q + 4];
                    mma_tf32(sA[n], a0, a1, a2, a3, b0, b1);
                }
            }
        }
        __syncthreads();       // all warps done reading Ks

        // ---- prefetch K(kt+1) while we do softmax + PV ----
        if (kt + 1 < ntile) {
            const float* base = gKh + (size_t)(s0 + BKV) * DQK;
#pragma unroll
            for (int i = 0; i < 12; i++) {
                int idx = tid + i * 256;
                int r = idx / 48, cw = idx - r * 48;
                CP16(Ks_u + (unsigned)(r * QSTR + cw * 4) * 4u, base + r * DQK + cw * 4);
            }
        }
        CP_COMMIT();           // pending: V(kt), K(kt+1)

        if (active) {
            // ---- scale + causal mask ----
#pragma unroll
            for (int n = 0; n < 8; n++) {
                int c0 = s0 + n * 8 + 2 * q;
                sA[n][0] = (c0     <= row_lo) ? sA[n][0] * QKSCALE : -1.0e30f;
                sA[n][1] = (c0 + 1 <= row_lo) ? sA[n][1] * QKSCALE : -1.0e30f;
                sA[n][2] = (c0     <= row_hi) ? sA[n][2] * QKSCALE : -1.0e30f;
                sA[n][3] = (c0 + 1 <= row_hi) ? sA[n][3] * QKSCALE : -1.0e30f;
            }

            // ---- online softmax in registers ----
            float tm_lo = -1.0e30f, tm_hi = -1.0e30f;
#pragma unroll
            for (int n = 0; n < 8; n++) {
                tm_lo = fmaxf(tm_lo, fmaxf(sA[n][0], sA[n][1]));
                tm_hi = fmaxf(tm_hi, fmaxf(sA[n][2], sA[n][3]));
            }
            tm_lo = fmaxf(tm_lo, __shfl_xor_sync(0xffffffffu, tm_lo, 1));
            tm_lo = fmaxf(tm_lo, __shfl_xor_sync(0xffffffffu, tm_lo, 2));
            tm_hi = fmaxf(tm_hi, __shfl_xor_sync(0xffffffffu, tm_hi, 1));
            tm_hi = fmaxf(tm_hi, __shfl_xor_sync(0xffffffffu, tm_hi, 2));

            float mn_lo = fmaxf(m_lo, tm_lo);
            float mn_hi = fmaxf(m_hi, tm_hi);
            float sc_lo = __expf(m_lo - mn_lo);
            float sc_hi = __expf(m_hi - mn_hi);

            float sum_lo = 0.f, sum_hi = 0.f;
#pragma unroll
            for (int n = 0; n < 8; n++) {
                sA[n][0] = __expf(sA[n][0] - mn_lo);
                sA[n][1] = __expf(sA[n][1] - mn_lo);
                sA[n][2] = __expf(sA[n][2] - mn_hi);
                sA[n][3] = __expf(sA[n][3] - mn_hi);
                sum_lo += sA[n][0] + sA[n][1];
                sum_hi += sA[n][2] + sA[n][3];
            }
            sum_lo += __shfl_xor_sync(0xffffffffu, sum_lo, 1);
            sum_lo += __shfl_xor_sync(0xffffffffu, sum_lo, 2);
            sum_hi += __shfl_xor_sync(0xffffffffu, sum_hi, 1);
            sum_hi += __shfl_xor_sync(0xffffffffu, sum_hi, 2);

            l_lo = l_lo * sc_lo + sum_lo;  m_lo = mn_lo;
            l_hi = l_hi * sc_hi + sum_hi;  m_hi = mn_hi;

#pragma unroll
            for (int n = 0; n < 16; n++) {
                oAcc[n][0] *= sc_lo;  oAcc[n][1] *= sc_lo;
                oAcc[n][2] *= sc_hi;  oAcc[n][3] *= sc_hi;
            }

            // ---- write P (tf32) to warp-private smem ----
            __syncwarp();
#pragma unroll
            for (int n = 0; n < 8; n++) {
                uint2 plo = make_uint2(f2tf(sA[n][0]), f2tf(sA[n][1]));
                uint2 phi = make_uint2(f2tf(sA[n][2]), f2tf(sA[n][3]));
                *(uint2*)&Pw[(g    ) * PSTR + n * 8 + 2 * q] = plo;
                *(uint2*)&Pw[(g + 8) * PSTR + n * 8 + 2 * q] = phi;
            }
            __syncwarp();
        }

        CP_WAIT1();            // V(kt) arrived   (pending: K(kt+1))
        __syncthreads();       // V visible

        // ---- O += P @ V ----
        if (active) {
#pragma unroll
            for (int kb = 0; kb < BKV / 8; kb++) {
                const int k0 = kb * 8;
                unsigned a0 = Pw[(g    ) * PSTR + k0 + q    ];
                unsigned a1 = Pw[(g + 8) * PSTR + k0 + q    ];
                unsigned a2 = Pw[(g    ) * PSTR + k0 + q + 4];
                unsigned a3 = Pw[(g + 8) * PSTR + k0 + q + 4];
#pragma unroll
                for (int n = 0; n < 16; n++) {
                    unsigned b0 = Vs[(k0 + q    ) * VSTR + n * 8 + g];
                    unsigned b1 = Vs[(k0 + q + 4) * VSTR + n * 8 + g];
                    mma_tf32(oAcc[n], a0, a1, a2, a3, b0, b1);
                }
            }
        }
        __syncthreads();       // all warps done reading Vs

        // ---- prefetch V(kt+1) ----
        if (kt + 1 < ntile) {
            const float* base = gVh + (size_t)(s0 + BKV) * VDIM;
#pragma unroll
            for (int i = 0; i < 8; i++) {
                int idx = tid + i * 256;
                int r = idx >> 5, cw = idx & 31;
                CP16(Vs_u + (unsigned)(r * VSTR + cw * 4) * 4u, base + r * VDIM + cw * 4);
            }
        }
        CP_COMMIT();           // pending: K(kt+1), V(kt+1)
    }

    // ---- epilogue: normalize + store ----
    const float il_lo = 1.0f / l_lo;
    const float il_hi = 1.0f / l_hi;
#pragma unroll
    for (int n = 0; n < 16; n++) {
        int col = h * VDIM + n * 8 + 2 * q;
        float2 vlo = make_float2(oAcc[n][0] * il_lo, oAcc[n][1] * il_lo);
        float2 vhi = make_float2(oAcc[n][2] * il_hi, oAcc[n][3] * il_hi);
        *(float2*)&out[(size_t)row_lo * (HH * VDIM) + col] = vlo;
        *(float2*)&out[(size_t)row_hi * (HH * VDIM) + col] = vhi;
    }
}

// ---------------------------------------------------------------------------
extern "C" void kernel_launch(void* const* d_in, const int* in_sizes, int n_in,
                              void* d_out, int out_size)
{
    const float* query = (const float*)d_in[0];  // (T, H, 192)
    const float* kc    = (const float*)d_in[1];  // (T, 512)
    const float* kpe   = (const float*)d_in[2];  // (T, 64)
    const float* wkv   = (const float*)d_in[3];  // (512, 4096)
    const float* wuv   = (const float*)d_in[4];  // (16, 512, 128)
    float* out = (float*)d_out;                  // (T, 2048)

    rope_fill_kernel<<<(HH * TT * 16 + 255) / 256, 256>>>(kpe);

    size_t gsmem = (size_t)(2 * GBUF) * sizeof(unsigned);   // 107,520 B
    cudaFuncSetAttribute(kv_gemm_kernel,
                         cudaFuncAttributeMaxDynamicSharedMemorySize, (int)gsmem);
    kv_gemm_kernel<<<dim3(32, 16), 256, gsmem>>>(kc, wkv, wuv);

    size_t smem = (size_t)(BQ * QSTR + BKV * QSTR + BKV * VSTR + NWARP * 16 * PSTR)
                  * sizeof(unsigned);   // 220,160 B
    cudaFuncSetAttribute(attn_kernel,
                         cudaFuncAttributeMaxDynamicSharedMemorySize, (int)smem);
    attn_kernel<<<dim3(TT / BQ, HH), 256, smem>>>(query, out);
}

// round 11
// speedup vs baseline: 1.6228x; 1.1081x over previous
#include <cuda_runtime.h>
#include <math.h>

// Problem constants
#define TT    2048
#define HH    16
#define NOPE  128
#define ROPE  64
#define DQK   192
#define LORA  512
#define VDIM  128
#define QKSCALE 0.07216878364870323f   // 1/sqrt(192)

// Attention tiling
#define BQ   128
#define BKV  64
#define NWARP 8
#define QSTR 200    // Qs/Ks row stride (192+8): stride%32==8 -> LDS.64 conflict-free
#define VTS  72     // Vt row stride (64+8):   stride%32==8 -> LDS.64 conflict-free
#define VBUF (128 * VTS)

// Stage-1 GEMM smem strides / buffer geometry
#define ASTR 36
#define BSTR 132
#define AHSZ (128 * ASTR)
#define GBUF (2 * AHSZ + 32 * BSTR)

// Scratch: K (d-dim pair-interleaved per octet, per head), V transposed [h][d][t]
__device__ float g_K[HH * TT * DQK];     // 25 MB
__device__ float g_Vt[HH * VDIM * TT];   // 16 MB

// ---------------------------------------------------------------------------
// helpers
// ---------------------------------------------------------------------------
__device__ __forceinline__ unsigned f2tf(float f) {
    unsigned u;
    asm("cvt.rna.tf32.f32 %0, %1;" : "=r"(u) : "f"(f));
    return u;
}

#define CP16(dst_u32, src_ptr) \
    asm volatile("cp.async.cg.shared.global [%0], [%1], 16;\n" \
                 :: "r"(dst_u32), "l"(src_ptr))
#define CP_COMMIT()   asm volatile("cp.async.commit_group;\n" ::)
#define CP_WAIT_ALL() asm volatile("cp.async.wait_group 0;\n" ::)

__device__ __forceinline__ void mma_tf32(float* c,
    unsigned a0, unsigned a1, unsigned a2, unsigned a3,
    unsigned b0, unsigned b1)
{
    asm volatile(
        "mma.sync.aligned.m16n8k8.row.col.f32.tf32.tf32.f32 "
        "{%0,%1,%2,%3}, {%4,%5,%6,%7}, {%8,%9}, {%0,%1,%2,%3};\n"
        : "+f"(c[0]), "+f"(c[1]), "+f"(c[2]), "+f"(c[3])
        : "r"(a0), "r"(a1), "r"(a2), "r"(a3), "r"(b0), "r"(b1));
}

// ---------------------------------------------------------------------------
// Stage 1: C(2048x4096) = k_c(2048x512) @ B(512x4096), tf32 MMA, split-A.
// Epilogue: K half -> g_K with per-octet pair-interleaved d (d: 0,2,4,6,1,3,5,7)
//           V half -> g_Vt transposed [h][d][t]
// ---------------------------------------------------------------------------
__global__ __launch_bounds__(256, 1) void kv_gemm_kernel(
    const float* __restrict__ kc,
    const float* __restrict__ wkv,
    const float* __restrict__ wuv)
{
    extern __shared__ unsigned gs[];

    const int bn  = blockIdx.x * 128;
    const int bm  = blockIdx.y * 128;
    const bool isV = (bn & 128) != 0;
    const int h   = bn >> 8;

    const int tid  = threadIdx.x;
    const int w    = tid >> 5;
    const int lane = tid & 31;
    const int g    = lane >> 2;
    const int q    = lane & 3;
    const int wm   = w & 3;
    const int wn   = w >> 2;
    const int m0   = wm * 32;
    const int n0   = wn * 64;

    const int ar  = tid >> 3;
    const int ac4 = tid & 7;
    const int bk  = tid >> 5;
    const int bj4 = tid & 31;

    float4 aReg[4], bReg[4];

#pragma unroll
    for (int i = 0; i < 4; i++)
        aReg[i] = *(const float4*)&kc[(size_t)(bm + ar + i * 32) * LORA + ac4 * 4];
#pragma unroll
    for (int i = 0; i < 4; i++) {
        int k = bk + i * 8;
        if (isV) bReg[i] = *(const float4*)&wuv[((size_t)h * LORA + k) * VDIM + bj4 * 4];
        else     bReg[i] = *(const float4*)&wkv[(size_t)k * (HH * 256) + bn + bj4 * 4];
    }

    float acc[2][8][4];
#pragma unroll
    for (int mt = 0; mt < 2; mt++)
#pragma unroll
        for (int nt = 0; nt < 8; nt++)
#pragma unroll
            for (int i = 0; i < 4; i++) acc[mt][nt][i] = 0.f;

    {
        unsigned* As_hi = gs;
        unsigned* As_lo = gs + AHSZ;
        unsigned* Bs    = gs + 2 * AHSZ;
#pragma unroll
        for (int i = 0; i < 4; i++) {
            float4 v = aReg[i];
            unsigned h0 = f2tf(v.x), h1 = f2tf(v.y), h2 = f2tf(v.z), h3 = f2tf(v.w);
            unsigned l0 = f2tf(v.x - __uint_as_float(h0));
            unsigned l1 = f2tf(v.y - __uint_as_float(h1));
            unsigned l2 = f2tf(v.z - __uint_as_float(h2));
            unsigned l3 = f2tf(v.w - __uint_as_float(h3));
            *(uint4*)&As_hi[(ar + i * 32) * ASTR + ac4 * 4] = make_uint4(h0, h1, h2, h3);
            *(uint4*)&As_lo[(ar + i * 32) * ASTR + ac4 * 4] = make_uint4(l0, l1, l2, l3);
        }
#pragma unroll
        for (int i = 0; i < 4; i++) {
            float4 v = bReg[i];
            *(uint4*)&Bs[(bk + i * 8) * BSTR + bj4 * 4] =
                make_uint4(f2tf(v.x), f2tf(v.y), f2tf(v.z), f2tf(v.w));
        }
    }

    for (int kt = 0; kt < 16; kt++) {
        __syncthreads();

        if (kt < 15) {
            const int k1 = (kt + 1) * 32;
#pragma unroll
            for (int i = 0; i < 4; i++)
                aReg[i] = *(const float4*)&kc[(size_t)(bm + ar + i * 32) * LORA + k1 + ac4 * 4];
#pragma unroll
            for (int i = 0; i < 4; i++) {
                int k = k1 + bk + i * 8;
                if (isV) bReg[i] = *(const float4*)&wuv[((size_t)h * LORA + k) * VDIM + bj4 * 4];
                else     bReg[i] = *(const float4*)&wkv[(size_t)k * (HH * 256) + bn + bj4 * 4];
            }
        }

        unsigned* As_hi = gs + (kt & 1) * GBUF;
        unsigned* As_lo = As_hi + AHSZ;
        unsigned* Bs    = As_hi + 2 * AHSZ;
#pragma unroll
        for (int ks = 0; ks < 4; ks++) {
            const int k0 = ks * 8;
            unsigned ah[2][4], al[2][4];
#pragma unroll
            for (int mt = 0; mt < 2; mt++) {
                int rb = (m0 + mt * 16 + g) * ASTR + k0 + q;
                ah[mt][0] = As_hi[rb];               ah[mt][1] = As_hi[rb + 8 * ASTR];
                ah[mt][2] = As_hi[rb + 4];           ah[mt][3] = As_hi[rb + 8 * ASTR + 4];
                al[mt][0] = As_lo[rb];               al[mt][1] = As_lo[rb + 8 * ASTR];
                al[mt][2] = As_lo[rb + 4];           al[mt][3] = As_lo[rb + 8 * ASTR + 4];
            }
#pragma unroll
            for (int nt = 0; nt < 8; nt++) {
                int cb = (k0 + q) * BSTR + n0 + nt * 8 + g;
                unsigned b0 = Bs[cb];
                unsigned b1 = Bs[cb + 4 * BSTR];
#pragma unroll
                for (int mt = 0; mt < 2; mt++) {
                    mma_tf32(acc[mt][nt], ah[mt][0], ah[mt][1], ah[mt][2], ah[mt][3], b0, b1);
                    mma_tf32(acc[mt][nt], al[mt][0], al[mt][1], al[mt][2], al[mt][3], b0, b1);
                }
            }
        }

        if (kt < 15) {
            unsigned* nAs_hi = gs + ((kt + 1) & 1) * GBUF;
            unsigned* nAs_lo = nAs_hi + AHSZ;
            unsigned* nBs    = nAs_hi + 2 * AHSZ;
#pragma unroll
            for (int i = 0; i < 4; i++) {
                float4 v = aReg[i];
                unsigned h0 = f2tf(v.x), h1 = f2tf(v.y), h2 = f2tf(v.z), h3 = f2tf(v.w);
                unsigned l0 = f2tf(v.x - __uint_as_float(h0));
                unsigned l1 = f2tf(v.y - __uint_as_float(h1));
                unsigned l2 = f2tf(v.z - __uint_as_float(h2));
                unsigned l3 = f2tf(v.w - __uint_as_float(h3));
                *(uint4*)&nAs_hi[(ar + i * 32) * ASTR + ac4 * 4] = make_uint4(h0, h1, h2, h3);
                *(uint4*)&nAs_lo[(ar + i * 32) * ASTR + ac4 * 4] = make_uint4(l0, l1, l2, l3);
            }
#pragma unroll
            for (int i = 0; i < 4; i++) {
                float4 v = bReg[i];
                *(uint4*)&nBs[(bk + i * 8) * BSTR + bj4 * 4] =
                    make_uint4(f2tf(v.x), f2tf(v.y), f2tf(v.z), f2tf(v.w));
            }
        }
    }

    // ---- epilogue ----
#pragma unroll
    for (int mt = 0; mt < 2; mt++) {
        int row0 = bm + m0 + mt * 16 + g;
        int row1 = row0 + 8;
#pragma unroll
        for (int nt = 0; nt < 8; nt++) {
            int col = n0 + nt * 8 + 2 * q;       // logical d within 128 (even)
            float c0 = __uint_as_float(f2tf(acc[mt][nt][0]));
            float c1 = __uint_as_float(f2tf(acc[mt][nt][1]));
            float c2 = __uint_as_float(f2tf(acc[mt][nt][2]));
            float c3 = __uint_as_float(f2tf(acc[mt][nt][3]));
            if (isV) {
                // transposed store: g_Vt[h][d][t]
                size_t b0 = ((size_t)h * VDIM + col) * TT;
                g_Vt[b0 + row0]      = c0;
                g_Vt[b0 + TT + row0] = c1;
                g_Vt[b0 + row1]      = c2;
                g_Vt[b0 + TT + row1] = c3;
            } else {
                // pair-interleaved d: delta(col), delta(col+1) = delta(col)+2
                int pd = (col & ~7) | (((col & 3) << 1) | ((col >> 2) & 1));
                g_K[((size_t)(h * TT + row0)) * DQK + pd]     = c0;
                g_K[((size_t)(h * TT + row0)) * DQK + pd + 2] = c1;
                g_K[((size_t)(h * TT + row1)) * DQK + pd]     = c2;
                g_K[((size_t)(h * TT + row1)) * DQK + pd + 2] = c3;
            }
        }
    }
}

// ---------------------------------------------------------------------------
// Rope fill: k_pe -> g_K cols [128,192) per head, tf32, pair-interleaved.
// ---------------------------------------------------------------------------
__global__ __launch_bounds__(256) void rope_fill_kernel(const float* __restrict__ kpe)
{
    int idx = blockIdx.x * 256 + threadIdx.x;     // HH*TT*16 float4 groups
    if (idx >= HH * TT * 16) return;
    int h   = idx >> 15;
    int rem = idx & 32767;
    int t   = rem >> 4;
    int c4  = rem & 15;
    int c   = c4 * 4;                              // logical rope col base (mult of 4)
    float4 v = *(const float4*)&kpe[t * ROPE + c];
    float* dst = &g_K[((size_t)(h * TT + t)) * DQK + NOPE];
    int pd = (c & ~7) | ((c & 4) ? 1 : 0);         // stride-2 within octet
    dst[pd]     = __uint_as_float(f2tf(v.x));
    dst[pd + 2] = __uint_as_float(f2tf(v.y));
    dst[pd + 4] = __uint_as_float(f2tf(v.z));
    dst[pd + 6] = __uint_as_float(f2tf(v.w));
}

// ---------------------------------------------------------------------------
// Stage 2: causal flash attention, tf32 MMA.
// - Q/K d-dim pair-interleaved in gmem -> all QK fragments are LDS.64
// - V transposed in gmem, contraction relabeled per octet -> P stays in
//   registers (no smem round-trip), V B-fragments are LDS.64
// - V double-buffered; 2 syncthreads per tile.
// ---------------------------------------------------------------------------
__global__ __launch_bounds__(256, 1) void attn_kernel(
    const float* __restrict__ query,
    float* __restrict__ out)
{
    extern __shared__ unsigned sm[];
    unsigned* Qs = sm;                       // BQ  * QSTR
    unsigned* Ks = Qs + BQ * QSTR;           // BKV * QSTR
    unsigned* Vt = Ks + BKV * QSTR;          // 2 * VBUF (128 d-rows x VTS)

    const int h    = blockIdx.y;
    const int qt   = (int)gridDim.x - 1 - (int)blockIdx.x;  // heavy tiles first
    const int q0   = qt * BQ;
    const int tid  = threadIdx.x;
    const int w    = tid >> 5;
    const int lane = tid & 31;
    const int g    = lane >> 2;
    const int q    = lane & 3;

    const unsigned Ks_u = (unsigned)__cvta_generic_to_shared(Ks);
    const unsigned Vt_u = (unsigned)__cvta_generic_to_shared(Vt);

    const float* gKh = g_K  + (size_t)h * TT * DQK;
    const float* gVh = g_Vt + (size_t)h * VDIM * TT;

    const int ntile = 2 * qt + 2;

    // ---- prologue: Q load (tf32, pair-interleaved scatter) ----
    for (int idx = tid; idx < BQ * 48; idx += 256) {
        int r = idx / 48, cw = idx - r * 48;
        int c = cw * 4;
        float4 v = *(const float4*)&query[((size_t)(q0 + r) * HH + h) * DQK + c];
        int pd = (c & ~7) | ((c & 4) ? 1 : 0);
        unsigned* d = &Qs[r * QSTR + pd];
        d[0] = f2tf(v.x); d[2] = f2tf(v.y); d[4] = f2tf(v.z); d[6] = f2tf(v.w);
    }
    {   // K tile 0 + V tile 0 (buffer 0), one commit group
#pragma unroll
        for (int i = 0; i < 12; i++) {
            int idx = tid + i * 256;
            int r = idx / 48, cw = idx - r * 48;
            CP16(Ks_u + (unsigned)(r * QSTR + cw * 4) * 4u, gKh + r * DQK + cw * 4);
        }
#pragma unroll
        for (int i = 0; i < 8; i++) {
            int idx = tid + i * 256;
            int d = idx >> 4, cw = idx & 15;
            CP16(Vt_u + (unsigned)(d * VTS + cw * 4) * 4u, gVh + (size_t)d * TT + cw * 4);
        }
        CP_COMMIT();
    }

    float oAcc[16][4];
#pragma unroll
    for (int n = 0; n < 16; n++)
#pragma unroll
        for (int i = 0; i < 4; i++) oAcc[n][i] = 0.f;

    float m_lo = -INFINITY, m_hi = -INFINITY;
    float l_lo = 0.f, l_hi = 0.f;

    const int row_lo   = q0 + w * 16 + g;
    const int row_hi   = row_lo + 8;
    const int rowmax_w = q0 + w * 16 + 15;

    float sA[8][4];

    for (int kt = 0; kt < ntile; kt++) {
        const int s0 = kt * BKV;
        const bool active = (s0 <= rowmax_w);

        CP_WAIT_ALL();         // K(kt) + V(kt) arrived
        __syncthreads();       // visible to all warps; Qs ready on kt==0

        // ---- S = Q @ K^T (all fragments LDS.64) ----
        if (active) {
#pragma unroll
            for (int n = 0; n < 8; n++)
#pragma unroll
                for (int i = 0; i < 4; i++) sA[n][i] = 0.f;
#pragma unroll
            for (int kb = 0; kb < DQK / 8; kb++) {
                const int k0 = kb * 8 + 2 * q;
                uint2 u0 = *(uint2*)&Qs[(w * 16 + g    ) * QSTR + k0];
                uint2 u1 = *(uint2*)&Qs[(w * 16 + g + 8) * QSTR + k0];
#pragma unroll
                for (int n = 0; n < 8; n++) {
                    uint2 b = *(uint2*)&Ks[(n * 8 + g) * QSTR + k0];
                    mma_tf32(sA[n], u0.x, u1.x, u0.y, u1.y, b.x, b.y);
                }
            }
        }
        __syncthreads();       // all warps done reading Ks (and prev Vt write-target free)

        // ---- prefetch K(kt+1) + V(kt+1) ----
        if (kt + 1 < ntile) {
            const float* kbase = gKh + (size_t)(s0 + BKV) * DQK;
#pragma unroll
            for (int i = 0; i < 12; i++) {
                int idx = tid + i * 256;
                int r = idx / 48, cw = idx - r * 48;
                CP16(Ks_u + (unsigned)(r * QSTR + cw * 4) * 4u, kbase + r * DQK + cw * 4);
            }
            const float* vbase = gVh + s0 + BKV;
            const unsigned vdst = Vt_u + (unsigned)(((kt + 1) & 1) * VBUF) * 4u;
#pragma unroll
            for (int i = 0; i < 8; i++) {
                int idx = tid + i * 256;
                int d = idx >> 4, cw = idx & 15;
                CP16(vdst + (unsigned)(d * VTS + cw * 4) * 4u, vbase + (size_t)d * TT + cw * 4);
            }
        }
        CP_COMMIT();

        if (active) {
            // ---- scale + causal mask ----
#pragma unroll
            for (int n = 0; n < 8; n++) {
                int c0 = s0 + n * 8 + 2 * q;
                sA[n][0] = (c0     <= row_lo) ? sA[n][0] * QKSCALE : -1.0e30f;
                sA[n][1] = (c0 + 1 <= row_lo) ? sA[n][1] * QKSCALE : -1.0e30f;
                sA[n][2] = (c0     <= row_hi) ? sA[n][2] * QKSCALE : -1.0e30f;
                sA[n][3] = (c0 + 1 <= row_hi) ? sA[n][3] * QKSCALE : -1.0e30f;
            }

            // ---- online softmax in registers ----
            float tm_lo = -1.0e30f, tm_hi = -1.0e30f;
#pragma unroll
            for (int n = 0; n < 8; n++) {
                tm_lo = fmaxf(tm_lo, fmaxf(sA[n][0], sA[n][1]));
                tm_hi = fmaxf(tm_hi, fmaxf(sA[n][2], sA[n][3]));
            }
            tm_lo = fmaxf(tm_lo, __shfl_xor_sync(0xffffffffu, tm_lo, 1));
            tm_lo = fmaxf(tm_lo, __shfl_xor_sync(0xffffffffu, tm_lo, 2));
            tm_hi = fmaxf(tm_hi, __shfl_xor_sync(0xffffffffu, tm_hi, 1));
            tm_hi = fmaxf(tm_hi, __shfl_xor_sync(0xffffffffu, tm_hi, 2));

            float mn_lo = fmaxf(m_lo, tm_lo);
            float mn_hi = fmaxf(m_hi, tm_hi);
            float sc_lo = __expf(m_lo - mn_lo);
            float sc_hi = __expf(m_hi - mn_hi);

            float sum_lo = 0.f, sum_hi = 0.f;
#pragma unroll
            for (int n = 0; n < 8; n++) {
                sA[n][0] = __expf(sA[n][0] - mn_lo);
                sA[n][1] = __expf(sA[n][1] - mn_lo);
                sA[n][2] = __expf(sA[n][2] - mn_hi);
                sA[n][3] = __expf(sA[n][3] - mn_hi);
                sum_lo += sA[n][0] + sA[n][1];
                sum_hi += sA[n][2] + sA[n][3];
            }
            sum_lo += __shfl_xor_sync(0xffffffffu, sum_lo, 1);
            sum_lo += __shfl_xor_sync(0xffffffffu, sum_lo, 2);
            sum_hi += __shfl_xor_sync(0xffffffffu, sum_hi, 1);
            sum_hi += __shfl_xor_sync(0xffffffffu, sum_hi, 2);

            l_lo = l_lo * sc_lo + sum_lo;  m_lo = mn_lo;
            l_hi = l_hi * sc_hi + sum_hi;  m_hi = mn_hi;

#pragma unroll
            for (int n = 0; n < 16; n++) {
                oAcc[n][0] *= sc_lo;  oAcc[n][1] *= sc_lo;
                oAcc[n][2] *= sc_hi;  oAcc[n][3] *= sc_hi;
            }

            // ---- P -> tf32 in registers (no smem round-trip) ----
            unsigned pA[8][4];
#pragma unroll
            for (int n = 0; n < 8; n++) {
                pA[n][0] = f2tf(sA[n][0]);  pA[n][1] = f2tf(sA[n][1]);
                pA[n][2] = f2tf(sA[n][2]);  pA[n][3] = f2tf(sA[n][3]);
            }

            // ---- O += P @ V : contraction relabeled per octet, so the
            //      register layout of P matches the A-fragment directly and
            //      V's B-fragment is one LDS.64 from the transposed tile ----
            unsigned* Vb = Vt + (kt & 1) * VBUF;
#pragma unroll
            for (int kb = 0; kb < BKV / 8; kb++) {
                const int k0 = kb * 8 + 2 * q;
#pragma unroll
                for (int n = 0; n < 16; n++) {
                    uint2 b = *(uint2*)&Vb[(n * 8 + g) * VTS + k0];
                    mma_tf32(oAcc[n], pA[kb][0], pA[kb][2], pA[kb][1], pA[kb][3], b.x, b.y);
                }
            }
        }
    }

    // ---- epilogue: normalize + store ----
    const float il_lo = 1.0f / l_lo;
    const float il_hi = 1.0f / l_hi;
#pragma unroll
    for (int n = 0; n < 16; n++) {
        int col = h * VDIM + n * 8 + 2 * q;
        float2 vlo = make_float2(oAcc[n][0] * il_lo, oAcc[n][1] * il_lo);
        float2 vhi = make_float2(oAcc[n][2] * il_hi, oAcc[n][3] * il_hi);
        *(float2*)&out[(size_t)row_lo * (HH * VDIM) + col] = vlo;
        *(float2*)&out[(size_t)row_hi * (HH * VDIM) + col] = vhi;
    }
}

// ---------------------------------------------------------------------------
extern "C" void kernel_launch(void* const* d_in, const int* in_sizes, int n_in,
                              void* d_out, int out_size)
{
    const float* query = (const float*)d_in[0];  // (T, H, 192)
    const float* kc    = (const float*)d_in[1];  // (T, 512)
    const float* kpe   = (const float*)d_in[2];  // (T, 64)
    const float* wkv   = (const float*)d_in[3];  // (512, 4096)
    const float* wuv   = (const float*)d_in[4];  // (16, 512, 128)
    float* out = (float*)d_out;                  // (T, 2048)

    rope_fill_kernel<<<(HH * TT * 16 + 255) / 256, 256>>>(kpe);

    size_t gsmem = (size_t)(2 * GBUF) * sizeof(unsigned);   // 107,520 B
    cudaFuncSetAttribute(kv_gemm_kernel,
                         cudaFuncAttributeMaxDynamicSharedMemorySize, (int)gsmem);
    kv_gemm_kernel<<<dim3(32, 16), 256, gsmem>>>(kc, wkv, wuv);

    size_t smem = (size_t)(BQ * QSTR + BKV * QSTR + 2 * VBUF) * sizeof(unsigned);
    // = 227,328 B
    cudaFuncSetAttribute(attn_kernel,
                         cudaFuncAttributeMaxDynamicSharedMemorySize, (int)smem);
    attn_kernel<<<dim3(TT / BQ, HH), 256, smem>>>(query, out);
}

// round 12
// speedup vs baseline: 1.8710x; 1.1530x over previous
#include <cuda_runtime.h>
#include <math.h>

// Problem constants
#define TT    2048
#define HH    16
#define NOPE  128
#define ROPE  64
#define DQK   192
#define LORA  512
#define VDIM  128
#define QKSCALE 0.07216878364870323f   // 1/sqrt(192)

// Attention tiling
#define BQ   128
#define BKV  64
#define NWARP 8
#define QSTR 200    // Qs/Ks row stride (192+8): stride%32==8 -> LDS.64 conflict-free
#define VTS  72     // Vt row stride (64+8):   stride%32==8 -> LDS.64 conflict-free
#define VBUF (128 * VTS)

// Stage-1 GEMM smem strides / buffer geometry (no split-A buffer anymore)
#define ASTR 36
#define BSTR 132
#define AHSZ (128 * ASTR)
#define GBUF (AHSZ + 32 * BSTR)        // 8832 words per buffer

// Scratch: K (d-dim pair-interleaved per octet, per head), V transposed [h][d][t]
__device__ float g_K[HH * TT * DQK];     // 25 MB
__device__ float g_Vt[HH * VDIM * TT];   // 16 MB

// ---------------------------------------------------------------------------
// helpers
// ---------------------------------------------------------------------------
__device__ __forceinline__ unsigned f2tf(float f) {
    unsigned u;
    asm("cvt.rna.tf32.f32 %0, %1;" : "=r"(u) : "f"(f));
    return u;
}

#define CP16(dst_u32, src_ptr) \
    asm volatile("cp.async.cg.shared.global [%0], [%1], 16;\n" \
                 :: "r"(dst_u32), "l"(src_ptr))
#define CP_COMMIT()   asm volatile("cp.async.commit_group;\n" ::)
#define CP_WAIT_ALL() asm volatile("cp.async.wait_group 0;\n" ::)

__device__ __forceinline__ void mma_tf32(float* c,
    unsigned a0, unsigned a1, unsigned a2, unsigned a3,
    unsigned b0, unsigned b1)
{
    asm volatile(
        "mma.sync.aligned.m16n8k8.row.col.f32.tf32.tf32.f32 "
        "{%0,%1,%2,%3}, {%4,%5,%6,%7}, {%8,%9}, {%0,%1,%2,%3};\n"
        : "+f"(c[0]), "+f"(c[1]), "+f"(c[2]), "+f"(c[3])
        : "r"(a0), "r"(a1), "r"(a2), "r"(a3), "r"(b0), "r"(b1));
}

// ---------------------------------------------------------------------------
// Stage 1: C(2048x4096) = k_c(2048x512) @ B(512x4096), tf32 MMA (single
// rounding on A and B). Double-buffered smem, register-staged prefetch,
// 2 CTAs/SM. Epilogue:
//   K half -> g_K pair-interleaved d per octet (+ rope cols folded in)
//   V half -> g_Vt transposed [h][d][t]
// ---------------------------------------------------------------------------
__global__ __launch_bounds__(256, 2) void kv_gemm_kernel(
    const float* __restrict__ kc,
    const float* __restrict__ wkv,
    const float* __restrict__ wuv,
    const float* __restrict__ kpe)
{
    extern __shared__ unsigned gs[];   // 2 buffers of GBUF words

    const int bn  = blockIdx.x * 128;
    const int bm  = blockIdx.y * 128;
    const bool isV = (bn & 128) != 0;
    const int h   = bn >> 8;

    const int tid  = threadIdx.x;
    const int w    = tid >> 5;
    const int lane = tid & 31;
    const int g    = lane >> 2;
    const int q    = lane & 3;
    const int wm   = w & 3;
    const int wn   = w >> 2;
    const int m0   = wm * 32;
    const int n0   = wn * 64;

    const int ar  = tid >> 3;
    const int ac4 = tid & 7;
    const int bk  = tid >> 5;
    const int bj4 = tid & 31;

    float4 aReg[4], bReg[4];

#pragma unroll
    for (int i = 0; i < 4; i++)
        aReg[i] = *(const float4*)&kc[(size_t)(bm + ar + i * 32) * LORA + ac4 * 4];
#pragma unroll
    for (int i = 0; i < 4; i++) {
        int k = bk + i * 8;
        if (isV) bReg[i] = *(const float4*)&wuv[((size_t)h * LORA + k) * VDIM + bj4 * 4];
        else     bReg[i] = *(const float4*)&wkv[(size_t)k * (HH * 256) + bn + bj4 * 4];
    }

    float acc[2][8][4];
#pragma unroll
    for (int mt = 0; mt < 2; mt++)
#pragma unroll
        for (int nt = 0; nt < 8; nt++)
#pragma unroll
            for (int i = 0; i < 4; i++) acc[mt][nt][i] = 0.f;

    {
        unsigned* As = gs;
        unsigned* Bs = gs + AHSZ;
#pragma unroll
        for (int i = 0; i < 4; i++) {
            float4 v = aReg[i];
            *(uint4*)&As[(ar + i * 32) * ASTR + ac4 * 4] =
                make_uint4(f2tf(v.x), f2tf(v.y), f2tf(v.z), f2tf(v.w));
        }
#pragma unroll
        for (int i = 0; i < 4; i++) {
            float4 v = bReg[i];
            *(uint4*)&Bs[(bk + i * 8) * BSTR + bj4 * 4] =
                make_uint4(f2tf(v.x), f2tf(v.y), f2tf(v.z), f2tf(v.w));
        }
    }

    for (int kt = 0; kt < 16; kt++) {
        __syncthreads();

        // ---- prefetch chunk kt+1 into registers (LDG before MMA) ----
        if (kt < 15) {
            const int k1 = (kt + 1) * 32;
#pragma unroll
            for (int i = 0; i < 4; i++)
                aReg[i] = *(const float4*)&kc[(size_t)(bm + ar + i * 32) * LORA + k1 + ac4 * 4];
#pragma unroll
            for (int i = 0; i < 4; i++) {
                int k = k1 + bk + i * 8;
                if (isV) bReg[i] = *(const float4*)&wuv[((size_t)h * LORA + k) * VDIM + bj4 * 4];
                else     bReg[i] = *(const float4*)&wkv[(size_t)k * (HH * 256) + bn + bj4 * 4];
            }
        }

        // ---- MMA on current buffer ----
        unsigned* As = gs + (kt & 1) * GBUF;
        unsigned* Bs = As + AHSZ;
#pragma unroll
        for (int ks = 0; ks < 4; ks++) {
            const int k0 = ks * 8;
            unsigned ah[2][4];
#pragma unroll
            for (int mt = 0; mt < 2; mt++) {
                int rb = (m0 + mt * 16 + g) * ASTR + k0 + q;
                ah[mt][0] = As[rb];               ah[mt][1] = As[rb + 8 * ASTR];
                ah[mt][2] = As[rb + 4];           ah[mt][3] = As[rb + 8 * ASTR + 4];
            }
#pragma unroll
            for (int nt = 0; nt < 8; nt++) {
                int cb = (k0 + q) * BSTR + n0 + nt * 8 + g;
                unsigned b0 = Bs[cb];
                unsigned b1 = Bs[cb + 4 * BSTR];
#pragma unroll
                for (int mt = 0; mt < 2; mt++)
                    mma_tf32(acc[mt][nt], ah[mt][0], ah[mt][1], ah[mt][2], ah[mt][3], b0, b1);
            }
        }

        // ---- convert + store chunk kt+1 into the other buffer ----
        if (kt < 15) {
            unsigned* nAs = gs + ((kt + 1) & 1) * GBUF;
            unsigned* nBs = nAs + AHSZ;
#pragma unroll
            for (int i = 0; i < 4; i++) {
                float4 v = aReg[i];
                *(uint4*)&nAs[(ar + i * 32) * ASTR + ac4 * 4] =
                    make_uint4(f2tf(v.x), f2tf(v.y), f2tf(v.z), f2tf(v.w));
            }
#pragma unroll
            for (int i = 0; i < 4; i++) {
                float4 v = bReg[i];
                *(uint4*)&nBs[(bk + i * 8) * BSTR + bj4 * 4] =
                    make_uint4(f2tf(v.x), f2tf(v.y), f2tf(v.z), f2tf(v.w));
            }
        }
    }

    // ---- epilogue ----
#pragma unroll
    for (int mt = 0; mt < 2; mt++) {
        int row0 = bm + m0 + mt * 16 + g;
        int row1 = row0 + 8;
#pragma unroll
        for (int nt = 0; nt < 8; nt++) {
            int col = n0 + nt * 8 + 2 * q;       // logical d within 128 (even)
            float c0 = __uint_as_float(f2tf(acc[mt][nt][0]));
            float c1 = __uint_as_float(f2tf(acc[mt][nt][1]));
            float c2 = __uint_as_float(f2tf(acc[mt][nt][2]));
            float c3 = __uint_as_float(f2tf(acc[mt][nt][3]));
            if (isV) {
                size_t b0 = ((size_t)h * VDIM + col) * TT;
                g_Vt[b0 + row0]      = c0;
                g_Vt[b0 + TT + row0] = c1;
                g_Vt[b0 + row1]      = c2;
                g_Vt[b0 + TT + row1] = c3;
            } else {
                int pd = (col & ~7) | (((col & 3) << 1) | ((col >> 2) & 1));
                g_K[((size_t)(h * TT + row0)) * DQK + pd]     = c0;
                g_K[((size_t)(h * TT + row0)) * DQK + pd + 2] = c1;
                g_K[((size_t)(h * TT + row1)) * DQK + pd]     = c2;
                g_K[((size_t)(h * TT + row1)) * DQK + pd + 2] = c3;
            }
        }
    }

    // ---- rope fill folded in: each K-half block covers (h, rows bm..bm+127)
    //      exactly once. tf32, pair-interleaved. ----
    if (!isV) {
#pragma unroll
        for (int i = 0; i < 8; i++) {
            int idx = tid + i * 256;               // 2048 float4 groups
            int r  = idx >> 4;
            int c4 = idx & 15;
            int c  = c4 * 4;
            float4 v = *(const float4*)&kpe[(size_t)(bm + r) * ROPE + c];
            float* dst = &g_K[((size_t)(h * TT + bm + r)) * DQK + NOPE];
            int pd = (c & ~7) | ((c & 4) ? 1 : 0);
            dst[pd]     = __uint_as_float(f2tf(v.x));
            dst[pd + 2] = __uint_as_float(f2tf(v.y));
            dst[pd + 4] = __uint_as_float(f2tf(v.z));
            dst[pd + 6] = __uint_as_float(f2tf(v.w));
        }
    }
}

// ---------------------------------------------------------------------------
// Stage 2: causal flash attention, tf32 MMA.  (unchanged — R11 proven)
// ---------------------------------------------------------------------------
__global__ __launch_bounds__(256, 1) void attn_kernel(
    const float* __restrict__ query,
    float* __restrict__ out)
{
    extern __shared__ unsigned sm[];
    unsigned* Qs = sm;                       // BQ  * QSTR
    unsigned* Ks = Qs + BQ * QSTR;           // BKV * QSTR
    unsigned* Vt = Ks + BKV * QSTR;          // 2 * VBUF

    const int h    = blockIdx.y;
    const int qt   = (int)gridDim.x - 1 - (int)blockIdx.x;  // heavy tiles first
    const int q0   = qt * BQ;
    const int tid  = threadIdx.x;
    const int w    = tid >> 5;
    const int lane = tid & 31;
    const int g    = lane >> 2;
    const int q    = lane & 3;

    const unsigned Ks_u = (unsigned)__cvta_generic_to_shared(Ks);
    const unsigned Vt_u = (unsigned)__cvta_generic_to_shared(Vt);

    const float* gKh = g_K  + (size_t)h * TT * DQK;
    const float* gVh = g_Vt + (size_t)h * VDIM * TT;

    const int ntile = 2 * qt + 2;

    // ---- prologue: Q load (tf32, pair-interleaved scatter) ----
    for (int idx = tid; idx < BQ * 48; idx += 256) {
        int r = idx / 48, cw = idx - r * 48;
        int c = cw * 4;
        float4 v = *(const float4*)&query[((size_t)(q0 + r) * HH + h) * DQK + c];
        int pd = (c & ~7) | ((c & 4) ? 1 : 0);
        unsigned* d = &Qs[r * QSTR + pd];
        d[0] = f2tf(v.x); d[2] = f2tf(v.y); d[4] = f2tf(v.z); d[6] = f2tf(v.w);
    }
    {   // K tile 0 + V tile 0 (buffer 0), one commit group
#pragma unroll
        for (int i = 0; i < 12; i++) {
            int idx = tid + i * 256;
            int r = idx / 48, cw = idx - r * 48;
            CP16(Ks_u + (unsigned)(r * QSTR + cw * 4) * 4u, gKh + r * DQK + cw * 4);
        }
#pragma unroll
        for (int i = 0; i < 8; i++) {
            int idx = tid + i * 256;
            int d = idx >> 4, cw = idx & 15;
            CP16(Vt_u + (unsigned)(d * VTS + cw * 4) * 4u, gVh + (size_t)d * TT + cw * 4);
        }
        CP_COMMIT();
    }

    float oAcc[16][4];
#pragma unroll
    for (int n = 0; n < 16; n++)
#pragma unroll
        for (int i = 0; i < 4; i++) oAcc[n][i] = 0.f;

    float m_lo = -INFINITY, m_hi = -INFINITY;
    float l_lo = 0.f, l_hi = 0.f;

    const int row_lo   = q0 + w * 16 + g;
    const int row_hi   = row_lo + 8;
    const int rowmax_w = q0 + w * 16 + 15;

    float sA[8][4];

    for (int kt = 0; kt < ntile; kt++) {
        const int s0 = kt * BKV;
        const bool active = (s0 <= rowmax_w);

        CP_WAIT_ALL();
        __syncthreads();

        // ---- S = Q @ K^T ----
        if (active) {
#pragma unroll
            for (int n = 0; n < 8; n++)
#pragma unroll
                for (int i = 0; i < 4; i++) sA[n][i] = 0.f;
#pragma unroll
            for (int kb = 0; kb < DQK / 8; kb++) {
                const int k0 = kb * 8 + 2 * q;
                uint2 u0 = *(uint2*)&Qs[(w * 16 + g    ) * QSTR + k0];
                uint2 u1 = *(uint2*)&Qs[(w * 16 + g + 8) * QSTR + k0];
#pragma unroll
                for (int n = 0; n < 8; n++) {
                    uint2 b = *(uint2*)&Ks[(n * 8 + g) * QSTR + k0];
                    mma_tf32(sA[n], u0.x, u1.x, u0.y, u1.y, b.x, b.y);
                }
            }
        }
        __syncthreads();

        // ---- prefetch K(kt+1) + V(kt+1) ----
        if (kt + 1 < ntile) {
            const float* kbase = gKh + (size_t)(s0 + BKV) * DQK;
#pragma unroll
            for (int i = 0; i < 12; i++) {
                int idx = tid + i * 256;
                int r = idx / 48, cw = idx - r * 48;
                CP16(Ks_u + (unsigned)(r * QSTR + cw * 4) * 4u, kbase + r * DQK + cw * 4);
            }
            const float* vbase = gVh + s0 + BKV;
            const unsigned vdst = Vt_u + (unsigned)(((kt + 1) & 1) * VBUF) * 4u;
#pragma unroll
            for (int i = 0; i < 8; i++) {
                int idx = tid + i * 256;
                int d = idx >> 4, cw = idx & 15;
                CP16(vdst + (unsigned)(d * VTS + cw * 4) * 4u, vbase + (size_t)d * TT + cw * 4);
            }
        }
        CP_COMMIT();

        if (active) {
            // ---- scale + causal mask ----
#pragma unroll
            for (int n = 0; n < 8; n++) {
                int c0 = s0 + n * 8 + 2 * q;
                sA[n][0] = (c0     <= row_lo) ? sA[n][0] * QKSCALE : -1.0e30f;
                sA[n][1] = (c0 + 1 <= row_lo) ? sA[n][1] * QKSCALE : -1.0e30f;
                sA[n][2] = (c0     <= row_hi) ? sA[n][2] * QKSCALE : -1.0e30f;
                sA[n][3] = (c0 + 1 <= row_hi) ? sA[n][3] * QKSCALE : -1.0e30f;
            }

            // ---- online softmax in registers ----
            float tm_lo = -1.0e30f, tm_hi = -1.0e30f;
#pragma unroll
            for (int n = 0; n < 8; n++) {
                tm_lo = fmaxf(tm_lo, fmaxf(sA[n][0], sA[n][1]));
                tm_hi = fmaxf(tm_hi, fmaxf(sA[n][2], sA[n][3]));
            }
            tm_lo = fmaxf(tm_lo, __shfl_xor_sync(0xffffffffu, tm_lo, 1));
            tm_lo = fmaxf(tm_lo, __shfl_xor_sync(0xffffffffu, tm_lo, 2));
            tm_hi = fmaxf(tm_hi, __shfl_xor_sync(0xffffffffu, tm_hi, 1));
            tm_hi = fmaxf(tm_hi, __shfl_xor_sync(0xffffffffu, tm_hi, 2));

            float mn_lo = fmaxf(m_lo, tm_lo);
            float mn_hi = fmaxf(m_hi, tm_hi);
            float sc_lo = __expf(m_lo - mn_lo);
            float sc_hi = __expf(m_hi - mn_hi);

            float sum_lo = 0.f, sum_hi = 0.f;
#pragma unroll
            for (int n = 0; n < 8; n++) {
                sA[n][0] = __expf(sA[n][0] - mn_lo);
                sA[n][1] = __expf(sA[n][1] - mn_lo);
                sA[n][2] = __expf(sA[n][2] - mn_hi);
                sA[n][3] = __expf(sA[n][3] - mn_hi);
                sum_lo += sA[n][0] + sA[n][1];
                sum_hi += sA[n][2] + sA[n][3];
            }
            sum_lo += __shfl_xor_sync(0xffffffffu, sum_lo, 1);
            sum_lo += __shfl_xor_sync(0xffffffffu, sum_lo, 2);
            sum_hi += __shfl_xor_sync(0xffffffffu, sum_hi, 1);
            sum_hi += __shfl_xor_sync(0xffffffffu, sum_hi, 2);

            l_lo = l_lo * sc_lo + sum_lo;  m_lo = mn_lo;
            l_hi = l_hi * sc_hi + sum_hi;  m_hi = mn_hi;

#pragma unroll
            for (int n = 0; n < 16; n++) {
                oAcc[n][0] *= sc_lo;  oAcc[n][1] *= sc_lo;
                oAcc[n][2] *= sc_hi;  oAcc[n][3] *= sc_hi;
            }

            // ---- P -> tf32 in registers ----
            unsigned pA[8][4];
#pragma unroll
            for (int n = 0; n < 8; n++) {
                pA[n][0] = f2tf(sA[n][0]);  pA[n][1] = f2tf(sA[n][1]);
                pA[n][2] = f2tf(sA[n][2]);  pA[n][3] = f2tf(sA[n][3]);
            }

            // ---- O += P @ V (relabeled contraction; V B-frag = LDS.64) ----
            unsigned* Vb = Vt + (kt & 1) * VBUF;
#pragma unroll
            for (int kb = 0; kb < BKV / 8; kb++) {
                const int k0 = kb * 8 + 2 * q;
#pragma unroll
                for (int n = 0; n < 16; n++) {
                    uint2 b = *(uint2*)&Vb[(n * 8 + g) * VTS + k0];
                    mma_tf32(oAcc[n], pA[kb][0], pA[kb][2], pA[kb][1], pA[kb][3], b.x, b.y);
                }
            }
        }
    }

    // ---- epilogue: normalize + store ----
    const float il_lo = 1.0f / l_lo;
    const float il_hi = 1.0f / l_hi;
#pragma unroll
    for (int n = 0; n < 16; n++) {
        int col = h * VDIM + n * 8 + 2 * q;
        float2 vlo = make_float2(oAcc[n][0] * il_lo, oAcc[n][1] * il_lo);
        float2 vhi = make_float2(oAcc[n][2] * il_hi, oAcc[n][3] * il_hi);
        *(float2*)&out[(size_t)row_lo * (HH * VDIM) + col] = vlo;
        *(float2*)&out[(size_t)row_hi * (HH * VDIM) + col] = vhi;
    }
}

// ---------------------------------------------------------------------------
extern "C" void kernel_launch(void* const* d_in, const int* in_sizes, int n_in,
                              void* d_out, int out_size)
{
    const float* query = (const float*)d_in[0];  // (T, H, 192)
    const float* kc    = (const float*)d_in[1];  // (T, 512)
    const float* kpe   = (const float*)d_in[2];  // (T, 64)
    const float* wkv   = (const float*)d_in[3];  // (512, 4096)
    const float* wuv   = (const float*)d_in[4];  // (16, 512, 128)
    float* out = (float*)d_out;                  // (T, 2048)

    size_t gsmem = (size_t)(2 * GBUF) * sizeof(unsigned);   // 70,656 B
    cudaFuncSetAttribute(kv_gemm_kernel,
                         cudaFuncAttributeMaxDynamicSharedMemorySize, (int)gsmem);
    kv_gemm_kernel<<<dim3(32, 16), 256, gsmem>>>(kc, wkv, wuv, kpe);

    size_t smem = (size_t)(BQ * QSTR + BKV * QSTR + 2 * VBUF) * sizeof(unsigned);
    // = 227,328 B
    cudaFuncSetAttribute(attn_kernel,
                         cudaFuncAttributeMaxDynamicSharedMemorySize, (int)smem);
    attn_kernel<<<dim3(TT / BQ, HH), 256, smem>>>(query, out);
}

// round 16
// speedup vs baseline: 2.3731x; 1.2684x over previous
#include <cuda_runtime.h>
#include <math.h>

// Problem constants
#define TT    2048
#define HH    16
#define NOPE  128
#define ROPE  64
#define DQK   192
#define LORA  512
#define VDIM  128
#define QKSCALE 0.07216878364870323f   // 1/sqrt(192)

// Attention tiling
#define BQ   128
#define BKV  64
#define QSTR 200    // Qs row stride: LDS.64 conflict-free (stride%32==8)
#define KSTR 208    // Ks row stride: LDS.128 conflict-free (stride%32==16)
#define VTS  72     // Vt row stride: LDS.64 conflict-free
#define VBUF (128 * VTS)

// Stage-1 GEMM smem strides / buffer geometry
#define ASTR 36
#define BSTR 132
#define AHSZ (128 * ASTR)
#define GBUF (AHSZ + 32 * BSTR)        // 8832 words per buffer

// Scratch: K (d-dim 16-group interleaved, per head), V transposed [h][d][t]
// d-permutation within each 16-col group: logical col c ->
//   o=(c&15)>>3, j=c&7, op=((j&3)<<1)|(j>>2), pos=(c&~15)+4*(op>>1)+2*o+(op&1)
// so thread q's mma k-slots for octet-pair (kb even, kb odd) are one uint4 at 4q.
__device__ float g_K[HH * TT * DQK];     // 25 MB
__device__ float g_Vt[HH * VDIM * TT];   // 16 MB

// ---------------------------------------------------------------------------
// helpers
// ---------------------------------------------------------------------------
__device__ __forceinline__ unsigned f2tf(float f) {
    unsigned u;
    asm("cvt.rna.tf32.f32 %0, %1;" : "=r"(u) : "f"(f));
    return u;
}

#define CP16(dst_u32, src_ptr) \
    asm volatile("cp.async.cg.shared.global [%0], [%1], 16;\n" \
                 :: "r"(dst_u32), "l"(src_ptr))
#define CP_COMMIT()   asm volatile("cp.async.commit_group;\n" ::)
#define CP_WAIT_ALL() asm volatile("cp.async.wait_group 0;\n" ::)

__device__ __forceinline__ void mma_tf32(float* c,
    unsigned a0, unsigned a1, unsigned a2, unsigned a3,
    unsigned b0, unsigned b1)
{
    asm volatile(
        "mma.sync.aligned.m16n8k8.row.col.f32.tf32.tf32.f32 "
        "{%0,%1,%2,%3}, {%4,%5,%6,%7}, {%8,%9}, {%0,%1,%2,%3};\n"
        : "+f"(c[0]), "+f"(c[1]), "+f"(c[2]), "+f"(c[3])
        : "r"(a0), "r"(a1), "r"(a2), "r"(a3), "r"(b0), "r"(b1));
}

// ---------------------------------------------------------------------------
// Stage 1: C(2048x4096) = k_c(2048x512) @ B(512x4096), tf32 MMA, 2 CTAs/SM,
// double-buffered smem + register-staged prefetch.
// Epilogue: K half -> g_K with 16-group d-interleave (+ rope fold), V -> g_Vt.
// ---------------------------------------------------------------------------
__global__ __launch_bounds__(256, 2) void kv_gemm_kernel(
    const float* __restrict__ kc,
    const float* __restrict__ wkv,
    const float* __restrict__ wuv,
    const float* __restrict__ kpe)
{
    extern __shared__ unsigned gs[];   // 2 buffers of GBUF words

    const int bn  = blockIdx.x * 128;
    const int bm  = blockIdx.y * 128;
    const bool isV = (bn & 128) != 0;
    const int h   = bn >> 8;

    const int tid  = threadIdx.x;
    const int w    = tid >> 5;
    const int lane = tid & 31;
    const int g    = lane >> 2;
    const int q    = lane & 3;
    const int wm   = w & 3;
    const int wn   = w >> 2;
    const int m0   = wm * 32;
    const int n0   = wn * 64;

    const int ar  = tid >> 3;
    const int ac4 = tid & 7;
    const int bk  = tid >> 5;
    const int bj4 = tid & 31;

    float4 aReg[4], bReg[4];

#pragma unroll
    for (int i = 0; i < 4; i++)
        aReg[i] = *(const float4*)&kc[(size_t)(bm + ar + i * 32) * LORA + ac4 * 4];
#pragma unroll
    for (int i = 0; i < 4; i++) {
        int k = bk + i * 8;
        if (isV) bReg[i] = *(const float4*)&wuv[((size_t)h * LORA + k) * VDIM + bj4 * 4];
        else     bReg[i] = *(const float4*)&wkv[(size_t)k * (HH * 256) + bn + bj4 * 4];
    }

    float acc[2][8][4];
#pragma unroll
    for (int mt = 0; mt < 2; mt++)
#pragma unroll
        for (int nt = 0; nt < 8; nt++)
#pragma unroll
            for (int i = 0; i < 4; i++) acc[mt][nt][i] = 0.f;

    {
        unsigned* As = gs;
        unsigned* Bs = gs + AHSZ;
#pragma unroll
        for (int i = 0; i < 4; i++) {
            float4 v = aReg[i];
            *(uint4*)&As[(ar + i * 32) * ASTR + ac4 * 4] =
                make_uint4(f2tf(v.x), f2tf(v.y), f2tf(v.z), f2tf(v.w));
        }
#pragma unroll
        for (int i = 0; i < 4; i++) {
            float4 v = bReg[i];
            *(uint4*)&Bs[(bk + i * 8) * BSTR + bj4 * 4] =
                make_uint4(f2tf(v.x), f2tf(v.y), f2tf(v.z), f2tf(v.w));
        }
    }

    for (int kt = 0; kt < 16; kt++) {
        __syncthreads();

        if (kt < 15) {
            const int k1 = (kt + 1) * 32;
#pragma unroll
            for (int i = 0; i < 4; i++)
                aReg[i] = *(const float4*)&kc[(size_t)(bm + ar + i * 32) * LORA + k1 + ac4 * 4];
#pragma unroll
            for (int i = 0; i < 4; i++) {
                int k = k1 + bk + i * 8;
                if (isV) bReg[i] = *(const float4*)&wuv[((size_t)h * LORA + k) * VDIM + bj4 * 4];
                else     bReg[i] = *(const float4*)&wkv[(size_t)k * (HH * 256) + bn + bj4 * 4];
            }
        }

        unsigned* As = gs + (kt & 1) * GBUF;
        unsigned* Bs = As + AHSZ;
#pragma unroll
        for (int ks = 0; ks < 4; ks++) {
            const int k0 = ks * 8;
            unsigned ah[2][4];
#pragma unroll
            for (int mt = 0; mt < 2; mt++) {
                int rb = (m0 + mt * 16 + g) * ASTR + k0 + q;
                ah[mt][0] = As[rb];               ah[mt][1] = As[rb + 8 * ASTR];
                ah[mt][2] = As[rb + 4];           ah[mt][3] = As[rb + 8 * ASTR + 4];
            }
#pragma unroll
            for (int nt = 0; nt < 8; nt++) {
                int cb = (k0 + q) * BSTR + n0 + nt * 8 + g;
                unsigned b0 = Bs[cb];
                unsigned b1 = Bs[cb + 4 * BSTR];
#pragma unroll
                for (int mt = 0; mt < 2; mt++)
                    mma_tf32(acc[mt][nt], ah[mt][0], ah[mt][1], ah[mt][2], ah[mt][3], b0, b1);
            }
        }

        if (kt < 15) {
            unsigned* nAs = gs + ((kt + 1) & 1) * GBUF;
            unsigned* nBs = nAs + AHSZ;
#pragma unroll
            for (int i = 0; i < 4; i++) {
                float4 v = aReg[i];
                *(uint4*)&nAs[(ar + i * 32) * ASTR + ac4 * 4] =
                    make_uint4(f2tf(v.x), f2tf(v.y), f2tf(v.z), f2tf(v.w));
            }
#pragma unroll
            for (int i = 0; i < 4; i++) {
                float4 v = bReg[i];
                *(uint4*)&nBs[(bk + i * 8) * BSTR + bj4 * 4] =
                    make_uint4(f2tf(v.x), f2tf(v.y), f2tf(v.z), f2tf(v.w));
            }
        }
    }

    // ---- epilogue ----
#pragma unroll
    for (int mt = 0; mt < 2; mt++) {
        int row0 = bm + m0 + mt * 16 + g;
        int row1 = row0 + 8;
#pragma unroll
        for (int nt = 0; nt < 8; nt++) {
            int col = n0 + nt * 8 + 2 * q;       // logical d within 128 (even)
            float c0 = __uint_as_float(f2tf(acc[mt][nt][0]));
            float c1 = __uint_as_float(f2tf(acc[mt][nt][1]));
            float c2 = __uint_as_float(f2tf(acc[mt][nt][2]));
            float c3 = __uint_as_float(f2tf(acc[mt][nt][3]));
            if (isV) {
                size_t b0 = ((size_t)h * VDIM + col) * TT;
                g_Vt[b0 + row0]      = c0;
                g_Vt[b0 + TT + row0] = c1;
                g_Vt[b0 + row1]      = c2;
                g_Vt[b0 + TT + row1] = c3;
            } else {
                // 16-group interleave: col -> p, col+1 -> p+4
                int r  = col & 15, o = r >> 3, j = r & 7;
                int op = ((j & 3) << 1) | (j >> 2);
                int p  = (col & ~15) + 4 * (op >> 1) + 2 * o + (op & 1);
                g_K[((size_t)(h * TT + row0)) * DQK + p]     = c0;
                g_K[((size_t)(h * TT + row0)) * DQK + p + 4] = c1;
                g_K[((size_t)(h * TT + row1)) * DQK + p]     = c2;
                g_K[((size_t)(h * TT + row1)) * DQK + p + 4] = c3;
            }
        }
    }

    // ---- rope fill folded in (K-half blocks only), 16-group interleave ----
    if (!isV) {
#pragma unroll
        for (int i = 0; i < 8; i++) {
            int idx = tid + i * 256;               // 2048 float4 groups
            int r  = idx >> 4;
            int c4 = idx & 15;
            int c  = c4 * 4;                       // local rope col (mult of 4)
            float4 v = *(const float4*)&kpe[(size_t)(bm + r) * ROPE + c];
            float* dst = &g_K[((size_t)(h * TT + bm + r)) * DQK + NOPE];
            int off = (c & ~15) + 2 * ((c >> 3) & 1) + ((c >> 2) & 1);
            dst[off]      = __uint_as_float(f2tf(v.x));
            dst[off + 4]  = __uint_as_float(f2tf(v.y));
            dst[off + 8]  = __uint_as_float(f2tf(v.z));
            dst[off + 12] = __uint_as_float(f2tf(v.w));
        }
    }
}

// ---------------------------------------------------------------------------
// Stage 2: causal flash attention, tf32 MMA.
// - K fragments: one LDS.128 per octet-pair (KSTR=208, conflict-free)
// - Q fragments: LDS.64 pairs from the same 16-group layout (QSTR=200)
// - P in registers; V transposed, relabeled contraction (LDS.64)
// - 1D grid with global LPT order: all heads' heavy q-tiles first.
// ---------------------------------------------------------------------------
__global__ __launch_bounds__(256, 1) void attn_kernel(
    const float* __restrict__ query,
    float* __restrict__ out)
{
    extern __shared__ unsigned sm[];
    unsigned* Qs = sm;                       // BQ  * QSTR
    unsigned* Ks = Qs + BQ * QSTR;           // BKV * KSTR
    unsigned* Vt = Ks + BKV * KSTR;          // 2 * VBUF

    const int bid  = blockIdx.x;
    const int h    = bid & 15;
    const int qt   = 15 - (bid >> 4);        // global LPT: heavy tiles first
    const int q0   = qt * BQ;
    const int tid  = threadIdx.x;
    const int w    = tid >> 5;
    const int lane = tid & 31;
    const int g    = lane >> 2;
    const int q    = lane & 3;

    const unsigned Ks_u = (unsigned)__cvta_generic_to_shared(Ks);
    const unsigned Vt_u = (unsigned)__cvta_generic_to_shared(Vt);

    const float* gKh = g_K  + (size_t)h * TT * DQK;
    const float* gVh = g_Vt + (size_t)h * VDIM * TT;

    const int ntile = 2 * qt + 2;

    // ---- prologue: Q load (tf32, 16-group interleaved scatter) ----
    for (int idx = tid; idx < BQ * 48; idx += 256) {
        int r = idx / 48, cw = idx - r * 48;
        int c = cw * 4;
        float4 v = *(const float4*)&query[((size_t)(q0 + r) * HH + h) * DQK + c];
        unsigned* d = &Qs[r * QSTR + (c & ~15) + 2 * ((c >> 3) & 1) + ((c >> 2) & 1)];
        d[0] = f2tf(v.x); d[4] = f2tf(v.y); d[8] = f2tf(v.z); d[12] = f2tf(v.w);
    }
    {   // K tile 0 + V tile 0 (buffer 0), one commit group
#pragma unroll
        for (int i = 0; i < 12; i++) {
            int idx = tid + i * 256;
            int r = idx / 48, cw = idx - r * 48;
            CP16(Ks_u + (unsigned)(r * KSTR + cw * 4) * 4u, gKh + r * DQK + cw * 4);
        }
#pragma unroll
        for (int i = 0; i < 8; i++) {
            int idx = tid + i * 256;
            int d = idx >> 4, cw = idx & 15;
            CP16(Vt_u + (unsigned)(d * VTS + cw * 4) * 4u, gVh + (size_t)d * TT + cw * 4);
        }
        CP_COMMIT();
    }

    float oAcc[16][4];
#pragma unroll
    for (int n = 0; n < 16; n++)
#pragma unroll
        for (int i = 0; i < 4; i++) oAcc[n][i] = 0.f;

    float m_lo = -INFINITY, m_hi = -INFINITY;
    float l_lo = 0.f, l_hi = 0.f;

    const int row_lo   = q0 + w * 16 + g;
    const int row_hi   = row_lo + 8;
    const int rowmax_w = q0 + w * 16 + 15;

    float sA[8][4];

    for (int kt = 0; kt < ntile; kt++) {
        const int s0 = kt * BKV;
        const bool active = (s0 <= rowmax_w);

        CP_WAIT_ALL();
        __syncthreads();

        // ---- S = Q @ K^T : 12 octet-pair steps, K via LDS.128 ----
        if (active) {
#pragma unroll
            for (int n = 0; n < 8; n++)
#pragma unroll
                for (int i = 0; i < 4; i++) sA[n][i] = 0.f;
#pragma unroll
            for (int kb2 = 0; kb2 < DQK / 16; kb2++) {
                const int k0 = kb2 * 16 + 4 * q;
                uint2 qe0 = *(uint2*)&Qs[(w * 16 + g    ) * QSTR + k0];
                uint2 qo0 = *(uint2*)&Qs[(w * 16 + g    ) * QSTR + k0 + 2];
                uint2 qe1 = *(uint2*)&Qs[(w * 16 + g + 8) * QSTR + k0];
                uint2 qo1 = *(uint2*)&Qs[(w * 16 + g + 8) * QSTR + k0 + 2];
#pragma unroll
                for (int n = 0; n < 8; n++) {
                    uint4 b = *(uint4*)&Ks[(n * 8 + g) * KSTR + k0];
                    mma_tf32(sA[n], qe0.x, qe1.x, qe0.y, qe1.y, b.x, b.y);
                    mma_tf32(sA[n], qo0.x, qo1.x, qo0.y, qo1.y, b.z, b.w);
                }
            }
        }
        __syncthreads();

        // ---- prefetch K(kt+1) + V(kt+1) ----
        if (kt + 1 < ntile) {
            const float* kbase = gKh + (size_t)(s0 + BKV) * DQK;
#pragma unroll
            for (int i = 0; i < 12; i++) {
                int idx = tid + i * 256;
                int r = idx / 48, cw = idx - r * 48;
                CP16(Ks_u + (unsigned)(r * KSTR + cw * 4) * 4u, kbase + r * DQK + cw * 4);
            }
            const float* vbase = gVh + s0 + BKV;
            const unsigned vdst = Vt_u + (unsigned)(((kt + 1) & 1) * VBUF) * 4u;
#pragma unroll
            for (int i = 0; i < 8; i++) {
                int idx = tid + i * 256;
                int d = idx >> 4, cw = idx & 15;
                CP16(vdst + (unsigned)(d * VTS + cw * 4) * 4u, vbase + (size_t)d * TT + cw * 4);
            }
        }
        CP_COMMIT();

        if (active) {
            // ---- scale + causal mask (S columns unaffected by d-permute) ----
#pragma unroll
            for (int n = 0; n < 8; n++) {
                int c0 = s0 + n * 8 + 2 * q;
                sA[n][0] = (c0     <= row_lo) ? sA[n][0] * QKSCALE : -1.0e30f;
                sA[n][1] = (c0 + 1 <= row_lo) ? sA[n][1] * QKSCALE : -1.0e30f;
                sA[n][2] = (c0     <= row_hi) ? sA[n][2] * QKSCALE : -1.0e30f;
                sA[n][3] = (c0 + 1 <= row_hi) ? sA[n][3] * QKSCALE : -1.0e30f;
            }

            // ---- online softmax in registers ----
            float tm_lo = -1.0e30f, tm_hi = -1.0e30f;
#pragma unroll
            for (int n = 0; n < 8; n++) {
                tm_lo = fmaxf(tm_lo, fmaxf(sA[n][0], sA[n][1]));
                tm_hi = fmaxf(tm_hi, fmaxf(sA[n][2], sA[n][3]));
            }
            tm_lo = fmaxf(tm_lo, __shfl_xor_sync(0xffffffffu, tm_lo, 1));
            tm_lo = fmaxf(tm_lo, __shfl_xor_sync(0xffffffffu, tm_lo, 2));
            tm_hi = fmaxf(tm_hi, __shfl_xor_sync(0xffffffffu, tm_hi, 1));
            tm_hi = fmaxf(tm_hi, __shfl_xor_sync(0xffffffffu, tm_hi, 2));

            float mn_lo = fmaxf(m_lo, tm_lo);
            float mn_hi = fmaxf(m_hi, tm_hi);
            float sc_lo = __expf(m_lo - mn_lo);
            float sc_hi = __expf(m_hi - mn_hi);

            float sum_lo = 0.f, sum_hi = 0.f;
#pragma unroll
            for (int n = 0; n < 8; n++) {
                sA[n][0] = __expf(sA[n][0] - mn_lo);
                sA[n][1] = __expf(sA[n][1] - mn_lo);
                sA[n][2] = __expf(sA[n][2] - mn_hi);
                sA[n][3] = __expf(sA[n][3] - mn_hi);
                sum_lo += sA[n][0] + sA[n][1];
                sum_hi += sA[n][2] + sA[n][3];
            }
            sum_lo += __shfl_xor_sync(0xffffffffu, sum_lo, 1);
            sum_lo += __shfl_xor_sync(0xffffffffu, sum_lo, 2);
            sum_hi += __shfl_xor_sync(0xffffffffu, sum_hi, 1);
            sum_hi += __shfl_xor_sync(0xffffffffu, sum_hi, 2);

            l_lo = l_lo * sc_lo + sum_lo;  m_lo = mn_lo;
            l_hi = l_hi * sc_hi + sum_hi;  m_hi = mn_hi;

#pragma unroll
            for (int n = 0; n < 16; n++) {
                oAcc[n][0] *= sc_lo;  oAcc[n][1] *= sc_lo;
                oAcc[n][2] *= sc_hi;  oAcc[n][3] *= sc_hi;
            }

            // ---- P -> tf32 in registers ----
            unsigned pA[8][4];
#pragma unroll
            for (int n = 0; n < 8; n++) {
                pA[n][0] = f2tf(sA[n][0]);  pA[n][1] = f2tf(sA[n][1]);
                pA[n][2] = f2tf(sA[n][2]);  pA[n][3] = f2tf(sA[n][3]);
            }

            // ---- O += P @ V (relabeled contraction; V B-frag = LDS.64) ----
            unsigned* Vb = Vt + (kt & 1) * VBUF;
#pragma unroll
            for (int kb = 0; kb < BKV / 8; kb++) {
                const int k0 = kb * 8 + 2 * q;
#pragma unroll
                for (int n = 0; n < 16; n++) {
                    uint2 b = *(uint2*)&Vb[(n * 8 + g) * VTS + k0];
                    mma_tf32(oAcc[n], pA[kb][0], pA[kb][2], pA[kb][1], pA[kb][3], b.x, b.y);
                }
            }
        }
    }

    // ---- epilogue: normalize + store ----
    const float il_lo = 1.0f / l_lo;
    const float il_hi = 1.0f / l_hi;
#pragma unroll
    for (int n = 0; n < 16; n++) {
        int col = h * VDIM + n * 8 + 2 * q;
        float2 vlo = make_float2(oAcc[n][0] * il_lo, oAcc[n][1] * il_lo);
        float2 vhi = make_float2(oAcc[n][2] * il_hi, oAcc[n][3] * il_hi);
        *(float2*)&out[(size_t)row_lo * (HH * VDIM) + col] = vlo;
        *(float2*)&out[(size_t)row_hi * (HH * VDIM) + col] = vhi;
    }
}

// ---------------------------------------------------------------------------
extern "C" void kernel_launch(void* const* d_in, const int* in_sizes, int n_in,
                              void* d_out, int out_size)
{
    const float* query = (const float*)d_in[0];  // (T, H, 192)
    const float* kc    = (const float*)d_in[1];  // (T, 512)
    const float* kpe   = (const float*)d_in[2];  // (T, 64)
    const float* wkv   = (const float*)d_in[3];  // (512, 4096)
    const float* wuv   = (const float*)d_in[4];  // (16, 512, 128)
    float* out = (float*)d_out;                  // (T, 2048)

    size_t gsmem = (size_t)(2 * GBUF) * sizeof(unsigned);   // 70,656 B
    cudaFuncSetAttribute(kv_gemm_kernel,
                         cudaFuncAttributeMaxDynamicSharedMemorySize, (int)gsmem);
    kv_gemm_kernel<<<dim3(32, 16), 256, gsmem>>>(kc, wkv, wuv, kpe);

    size_t smem = (size_t)(BQ * QSTR + BKV * KSTR + 2 * VBUF) * sizeof(unsigned);
    // = 229,376 B
    cudaFuncSetAttribute(attn_kernel,
                         cudaFuncAttributeMaxDynamicSharedMemorySize, (int)smem);
    attn_kernel<<<dim3(HH * (TT / BQ)), 256, smem>>>(query, out);
}